// round 14
// baseline (speedup 1.0000x reference)
#include <cuda_runtime.h>
#include <cstdint>

#define B_  4
#define S_  2048
#define D_  1024
#define H_  16
#define DK_ 64
#define SCALE_ 0.125f          // 1/sqrt(64), exact power of two
#define LN_EPS_ 1e-5f

#define GM 8192                // B_*S_
#define GN 1024
#define GK 1024

#define BSD ((size_t)B_ * S_ * D_)            // 8,388,608
#define NMASK ((size_t)B_ * S_ * S_)          // 16,777,216

// ---------------- device scratch --------------------------------------------
__device__ float g_Q[BSD];
__device__ float g_K[BSD];
__device__ float g_V[BSD];
__device__ float g_ctx[BSD];
__device__ float g_out[BSD];
__device__ float g_Wr[(size_t)D_ * D_];
__device__ float g_inv[(size_t)B_ * H_ * S_];
__device__ unsigned char g_mask[NMASK];
__device__ int g_mask_mode;

// ---------------- helpers ----------------------------------------------------
__device__ __forceinline__ float tf32r(float x) {
    uint32_t u; asm("cvt.rna.tf32.f32 %0, %1;" : "=r"(u) : "f"(x));
    return __uint_as_float(u);
}
__device__ __forceinline__ uint32_t uf(float x) { return __float_as_uint(x); }

__device__ __forceinline__ void mma8(float4& d, const uint32_t a[4], const uint32_t b[2]) {
    asm volatile(
        "mma.sync.aligned.m16n8k8.row.col.f32.tf32.tf32.f32 "
        "{%0,%1,%2,%3}, {%4,%5,%6,%7}, {%8,%9}, {%0,%1,%2,%3};"
        : "+f"(d.x), "+f"(d.y), "+f"(d.z), "+f"(d.w)
        : "r"(a[0]), "r"(a[1]), "r"(a[2]), "r"(a[3]), "r"(b[0]), "r"(b[1]));
}

__device__ __forceinline__ void cpa16(void* s, const void* g) {
    uint32_t sa = (uint32_t)__cvta_generic_to_shared(s);
    asm volatile("cp.async.cg.shared.global [%0], [%1], 16;" :: "r"(sa), "l"(g));
}
__device__ __forceinline__ void cpa_commit() { asm volatile("cp.async.commit_group;"); }
__device__ __forceinline__ void cpa_wait0()  { asm volatile("cp.async.wait_group 0;"); }

// ---------------- tf32 pre-round (RNA) ---------------------------------------
__global__ __launch_bounds__(256) void round_copy(const float* __restrict__ src,
                                                  float* __restrict__ dst, size_t n4)
{
    const size_t stride = (size_t)gridDim.x * blockDim.x;
    const float4* s4 = (const float4*)src;
    float4* d4 = (float4*)dst;
    for (size_t i = (size_t)blockIdx.x * blockDim.x + threadIdx.x; i < n4; i += stride) {
        float4 v = s4[i];
        d4[i] = make_float4(tf32r(v.x), tf32r(v.y), tf32r(v.z), tf32r(v.w));
    }
}

// ---------------- mask dtype detection --------------------------------------
__global__ void detect_mask_kernel(const unsigned int* __restrict__ w) {
    __shared__ unsigned int sh;
    if (threadIdx.x == 0) sh = 0u;
    __syncthreads();
    unsigned int acc = 0u;
    for (int i = threadIdx.x; i < 65536; i += 256) acc |= w[i];
    atomicOr(&sh, acc);
    __syncthreads();
    if (threadIdx.x == 0) {
        unsigned int o = sh;
        int mode;
        if (o & 0x0000FF00u)              mode = 0; // uint8 bools
        else if ((o & 0xFFFFFF00u) == 0u) mode = 1; // int32 0/1
        else                              mode = 2; // float32 0/1
        g_mask_mode = mode;
    }
}

__global__ void convert_mask_kernel(const void* __restrict__ mptr) {
    const int mode = g_mask_mode;
    const size_t n = NMASK;
    const size_t stride = (size_t)gridDim.x * blockDim.x;
    for (size_t i = (size_t)blockIdx.x * blockDim.x + threadIdx.x; i < n; i += stride) {
        unsigned char v;
        if (mode == 0)      v = ((const unsigned char*)mptr)[i];
        else if (mode == 1) v = (unsigned char)(((const int*)mptr)[i] != 0);
        else                v = (unsigned char)(((const float*)mptr)[i] != 0.0f);
        g_mask[i] = v;
    }
}

// ---------------- tf32 TC GEMM, cp.async double-buffered ---------------------
// C = A @ W^T + bias (+resid). A,W pre-rounded tf32. Block 128x128, kc=32.
// 8 warps = 4m x 2n, warp tile 32x64. DYNAMIC smem (73.7KB > 48KB static cap).
#define SA 36
#define GEMM_SMEM_BYTES (2 * 2 * 128 * SA * 4)   // 73728
__global__ __launch_bounds__(256, 2) void gemm_tc(
    const float* __restrict__ A, const float* __restrict__ W,
    const float* __restrict__ bias, const float* __restrict__ resid,
    float* __restrict__ C, int round_out)
{
    extern __shared__ float gsm[];
    float* Asb = gsm;                      // 2 stages x 128*SA
    float* Wsb = gsm + 2 * 128 * SA;
    const int t = threadIdx.x;
    const int lane = t & 31, w = t >> 5;
    const int g = lane >> 2, tig = lane & 3;
    const int wq = w >> 1, wn = w & 1;
    const int bm = blockIdx.y * 128, bn = blockIdx.x * 128;
    const int lrow = t >> 1, lseg = (t & 1) * 16;

    const float* Ag = A + (size_t)(bm + lrow) * GK + lseg;
    const float* Wg = W + (size_t)(bn + lrow) * GK + lseg;

    float4 acc[2][8];
#pragma unroll
    for (int i = 0; i < 2; i++)
#pragma unroll
        for (int j = 0; j < 8; j++) acc[i][j] = make_float4(0.f, 0.f, 0.f, 0.f);

    // preload stage 0
    {
        float* da = Asb + lrow * SA + lseg;
        float* dw = Wsb + lrow * SA + lseg;
#pragma unroll
        for (int p = 0; p < 4; p++) { cpa16(da + 4 * p, Ag + 4 * p); cpa16(dw + 4 * p, Wg + 4 * p); }
        cpa_commit();
    }

    for (int it = 0; it < GK / 32; it++) {
        cpa_wait0();
        __syncthreads();
        if (it + 1 < GK / 32) {
            const int k0 = (it + 1) * 32;
            const int st = (it + 1) & 1;
            float* da = Asb + st * (128 * SA) + lrow * SA + lseg;
            float* dw = Wsb + st * (128 * SA) + lrow * SA + lseg;
#pragma unroll
            for (int p = 0; p < 4; p++) { cpa16(da + 4 * p, Ag + k0 + 4 * p); cpa16(dw + 4 * p, Wg + k0 + 4 * p); }
            cpa_commit();
        }
        const float* as = Asb + (it & 1) * (128 * SA);
        const float* ws = Wsb + (it & 1) * (128 * SA);
#pragma unroll
        for (int ks = 0; ks < 4; ks++) {
            const int kc = ks * 8;
            uint32_t a[2][4], bfr[8][2];
#pragma unroll
            for (int i = 0; i < 2; i++) {
                const int r = 32 * wq + 16 * i + g;
                a[i][0] = uf(as[r * SA + kc + tig]);
                a[i][1] = uf(as[(r + 8) * SA + kc + tig]);
                a[i][2] = uf(as[r * SA + kc + tig + 4]);
                a[i][3] = uf(as[(r + 8) * SA + kc + tig + 4]);
            }
#pragma unroll
            for (int j = 0; j < 8; j++) {
                const int n0 = 64 * wn + 8 * j + g;
                bfr[j][0] = uf(ws[n0 * SA + kc + tig]);
                bfr[j][1] = uf(ws[n0 * SA + kc + tig + 4]);
            }
#pragma unroll
            for (int i = 0; i < 2; i++)
#pragma unroll
                for (int j = 0; j < 8; j++) mma8(acc[i][j], a[i], bfr[j]);
        }
    }
#pragma unroll
    for (int i = 0; i < 2; i++) {
        const int r0 = bm + 32 * wq + 16 * i + g;
#pragma unroll
        for (int j = 0; j < 8; j++) {
            const int cg = bn + 64 * wn + 8 * j + 2 * tig;
            float2 bb = *(const float2*)&bias[cg];
            float2 o0 = make_float2(acc[i][j].x + bb.x, acc[i][j].y + bb.y);
            float2 o1 = make_float2(acc[i][j].z + bb.x, acc[i][j].w + bb.y);
            if (resid) {
                float2 ra = *(const float2*)&resid[(size_t)r0 * GN + cg];
                float2 rb = *(const float2*)&resid[(size_t)(r0 + 8) * GN + cg];
                o0.x += ra.x; o0.y += ra.y; o1.x += rb.x; o1.y += rb.y;
            }
            if (round_out) {
                o0.x = tf32r(o0.x); o0.y = tf32r(o0.y);
                o1.x = tf32r(o1.x); o1.y = tf32r(o1.y);
            }
            *(float2*)&C[(size_t)r0 * GN + cg] = o0;
            *(float2*)&C[(size_t)(r0 + 8) * GN + cg] = o1;
        }
    }
}

// ---------------- rowsum pre-pass: QK + exp + rowsum only --------------------
// qtile=128, ktile=64, 512 threads (16 warps, 4q x 4k). Same tf32 fragment
// math as attn_tc so scores bit-match. Writes 1/rowsum to g_inv.
#define STH 512
#define AST 68   // K/Q stride
#define SUMS_RED 8704                      // Ksb = 2*64*AST = 8704 floats
#define SUMS_MS  10752                     // red = 128*16 = 2048; then mask bytes
#define SUMS_SMEM_BYTES ((10752 + 4096) * 4)   // 59392 (Q staging aliases [0,8704))
__global__ __launch_bounds__(STH) void attn_sums()
{
    extern __shared__ float sm[];
    float* Ksb = sm;
    float* red = sm + SUMS_RED;
    char*  Msb = (char*)(sm + SUMS_MS);

    const int t = threadIdx.x;
    const int lane = t & 31, w = t >> 5;
    const int g = lane >> 2, tig = lane & 3;
    const int wq = w >> 2, wn = w & 3;
    const int qt = blockIdx.x, h = blockIdx.y, b = blockIdx.z;
    const int qg0 = qt * 128;
    const size_t qrowg = (size_t)(b * S_) + qg0;
    const int qlr = t >> 2;                       // 0..127
    const int kr = t >> 3, kq = t & 7;            // 64-row staging

    const float* Kb = g_K + (size_t)(b * S_) * D_ + h * DK_;
    const unsigned char* Mb = g_mask + (size_t)(b * S_ + qg0) * S_;
    const size_t inv_row0 = (size_t)(h * B_ + b) * S_ + qg0;

    // stage Q into sm[0..8704) (aliased with Ksb/red; freed before preload)
    {
        const float* Qg = g_Q + (qrowg + qlr) * D_ + h * DK_ + (t & 3) * 16;
        float* dst = &sm[qlr * AST + (t & 3) * 16];
#pragma unroll
        for (int jj = 0; jj < 4; jj++)
            *(float4*)(dst + 4 * jj) = *(const float4*)(Qg + 4 * jj);
    }
    __syncthreads();
    uint32_t qa[2][8][4];
#pragma unroll
    for (int i = 0; i < 2; i++) {
        const int r = 32 * wq + 16 * i + g;
#pragma unroll
        for (int ks = 0; ks < 8; ks++) {
            const int kd = ks * 8;
            qa[i][ks][0] = uf(SCALE_ * sm[r * AST + kd + tig]);
            qa[i][ks][1] = uf(SCALE_ * sm[(r + 8) * AST + kd + tig]);
            qa[i][ks][2] = uf(SCALE_ * sm[r * AST + kd + tig + 4]);
            qa[i][ks][3] = uf(SCALE_ * sm[(r + 8) * AST + kd + tig + 4]);
        }
    }
    __syncthreads();   // Q staging region now free for Ksb/red

    // preload stage 0
    {
        float* dk = Ksb + kr * AST + kq * 8;
        const float* Kg = Kb + (size_t)kr * D_ + kq * 8;
        cpa16(dk, Kg); cpa16(dk + 4, Kg + 4);
        char* dm = Msb + qlr * 64 + (t & 3) * 16;
        const unsigned char* mg = Mb + (size_t)qlr * S_ + (t & 3) * 16;
        cpa16(dm, mg);
        cpa_commit();
    }

    float rs[2][2] = {{0.f, 0.f}, {0.f, 0.f}};

    for (int ic = 0; ic < S_ / 64; ic++) {
        const int kc = ic * 64;
        cpa_wait0();
        __syncthreads();
        if (ic + 1 < S_ / 64) {
            const int st = (ic + 1) & 1;
            float* dk = Ksb + st * (64 * AST) + kr * AST + kq * 8;
            const float* Kg = Kb + (size_t)(kc + 64 + kr) * D_ + kq * 8;
            cpa16(dk, Kg); cpa16(dk + 4, Kg + 4);
            char* dm = Msb + st * 8192 + qlr * 64 + (t & 3) * 16;
            const unsigned char* mg = Mb + (size_t)qlr * S_ + kc + 64 + (t & 3) * 16;
            cpa16(dm, mg);
            cpa_commit();
        }
        const float* Ks = Ksb + (ic & 1) * (64 * AST);
        const char*  Ms = Msb + (ic & 1) * 8192;

        float4 s[2][2];
#pragma unroll
        for (int i = 0; i < 2; i++)
#pragma unroll
            for (int j = 0; j < 2; j++) s[i][j] = make_float4(0.f, 0.f, 0.f, 0.f);
#pragma unroll
        for (int ks = 0; ks < 8; ks++) {
            const int kd = ks * 8;
            uint32_t bf[2][2];
#pragma unroll
            for (int j = 0; j < 2; j++) {
                const int n0 = 16 * wn + 8 * j + g;
                bf[j][0] = uf(Ks[n0 * AST + kd + tig]);
                bf[j][1] = uf(Ks[n0 * AST + kd + tig + 4]);
            }
#pragma unroll
            for (int i = 0; i < 2; i++)
#pragma unroll
                for (int j = 0; j < 2; j++) mma8(s[i][j], qa[i][ks], bf[j]);
        }
#pragma unroll
        for (int i = 0; i < 2; i++) {
            const int r = 32 * wq + 16 * i + g;
#pragma unroll
            for (int j = 0; j < 2; j++) {
                const int c0 = 16 * wn + 8 * j + 2 * tig;
                float p0 = Ms[r * 64 + c0]           ? 0.f : __expf(s[i][j].x);
                float p1 = Ms[r * 64 + c0 + 1]       ? 0.f : __expf(s[i][j].y);
                float p2 = Ms[(r + 8) * 64 + c0]     ? 0.f : __expf(s[i][j].z);
                float p3 = Ms[(r + 8) * 64 + c0 + 1] ? 0.f : __expf(s[i][j].w);
                rs[i][0] += p0 + p1; rs[i][1] += p2 + p3;
            }
        }
    }

    __syncthreads();
#pragma unroll
    for (int i = 0; i < 2; i++) {
        const int r = 32 * wq + 16 * i + g;
        red[r * 16 + wn * 4 + tig]       = rs[i][0];
        red[(r + 8) * 16 + wn * 4 + tig] = rs[i][1];
    }
    __syncthreads();
    if (t < 128) {
        float ssum = 0.f;
#pragma unroll
        for (int j = 0; j < 16; j++) ssum += red[t * 16 + j];
        g_inv[inv_row0 + t] = 1.0f / ssum;
    }
}

// ---------------- single-pass TC attention, 512 threads (16 warps) -----------
// inv preloaded from g_inv: writes NORMALIZED attn directly (no norm pass),
// normalized PV -> ctx.
#define ATH 512
#define VST 72   // V stride (288B)
#define OFF_KS  8704                       // Ps = 128*AST = 8704 floats
#define OFF_VS  (OFF_KS + 2 * 64 * AST)    // 17408
#define OFF_INV (OFF_VS + 2 * 64 * VST)    // 26624
#define OFF_MS  (OFF_INV + 128)            // 26752 floats; then 2*8192 mask bytes
#define ATTN_SMEM_BYTES (OFF_MS * 4 + 2 * 8192)   // 123392
__global__ __launch_bounds__(ATH) void attn_tc(float* __restrict__ attn_out)
{
    extern __shared__ float sm[];
    float* Ps   = sm;
    float* Ksb  = sm + OFF_KS;
    float* Vsb  = sm + OFF_VS;
    float* invs = sm + OFF_INV;
    char*  Msb  = (char*)(sm + OFF_MS);

    const int t = threadIdx.x;
    const int lane = t & 31, w = t >> 5;
    const int g = lane >> 2, tig = lane & 3;
    const int wq = w >> 2, wn = w & 3;            // 4q x 4k warp grid
    const int qt = blockIdx.x, h = blockIdx.y, b = blockIdx.z;
    const int qg0 = qt * 128;
    const size_t qrowg = (size_t)(b * S_) + qg0;
    const int qlr = t >> 2, qseg = (t & 3) * 16;  // 128-row staging
    const int kr = t >> 3, kq = t & 7;            // 64-row staging

    const float* Kb = g_K + (size_t)(b * S_) * D_ + h * DK_;
    const float* Vb = g_V + (size_t)(b * S_) * D_ + h * DK_;
    const unsigned char* Mb = g_mask + (size_t)(b * S_ + qg0) * S_;
    const size_t attn_row0 = (size_t)(h * B_ + b) * S_ + qg0;

    // stage Q + preload inv
    if (t < 128) invs[t] = g_inv[attn_row0 + t];
    {
        const float* Qg = g_Q + (qrowg + qlr) * D_ + h * DK_ + qseg;
        float* dst = &Ps[qlr * AST + qseg];
#pragma unroll
        for (int jj = 0; jj < 4; jj++)
            *(float4*)(dst + 4 * jj) = *(const float4*)(Qg + 4 * jj);
    }
    __syncthreads();
    uint32_t qa[2][8][4];
#pragma unroll
    for (int i = 0; i < 2; i++) {
        const int r = 32 * wq + 16 * i + g;
#pragma unroll
        for (int ks = 0; ks < 8; ks++) {
            const int kd = ks * 8;
            qa[i][ks][0] = uf(SCALE_ * Ps[r * AST + kd + tig]);
            qa[i][ks][1] = uf(SCALE_ * Ps[(r + 8) * AST + kd + tig]);
            qa[i][ks][2] = uf(SCALE_ * Ps[r * AST + kd + tig + 4]);
            qa[i][ks][3] = uf(SCALE_ * Ps[(r + 8) * AST + kd + tig + 4]);
        }
    }

    float inv[2][2];
#pragma unroll
    for (int i = 0; i < 2; i++) {
        const int r = 32 * wq + 16 * i + g;
        inv[i][0] = invs[r]; inv[i][1] = invs[r + 8];
    }

    // preload stage 0
    {
        float* dk = Ksb + kr * AST + kq * 8;
        float* dv = Vsb + kr * VST + kq * 8;
        const float* Kg = Kb + (size_t)kr * D_ + kq * 8;
        const float* Vg = Vb + (size_t)kr * D_ + kq * 8;
        cpa16(dk, Kg); cpa16(dk + 4, Kg + 4);
        cpa16(dv, Vg); cpa16(dv + 4, Vg + 4);
        char* dm = Msb + qlr * 64 + (t & 3) * 16;
        const unsigned char* mg = Mb + (size_t)qlr * S_ + (t & 3) * 16;
        cpa16(dm, mg);
        cpa_commit();
    }

    float4 o[2][2];
#pragma unroll
    for (int i = 0; i < 2; i++)
#pragma unroll
        for (int j = 0; j < 2; j++) o[i][j] = make_float4(0.f, 0.f, 0.f, 0.f);

    for (int ic = 0; ic < S_ / 64; ic++) {
        const int kc = ic * 64;
        cpa_wait0();
        __syncthreads();
        if (ic + 1 < S_ / 64) {
            const int st = (ic + 1) & 1;
            float* dk = Ksb + st * (64 * AST) + kr * AST + kq * 8;
            float* dv = Vsb + st * (64 * VST) + kr * VST + kq * 8;
            const float* Kg = Kb + (size_t)(kc + 64 + kr) * D_ + kq * 8;
            const float* Vg = Vb + (size_t)(kc + 64 + kr) * D_ + kq * 8;
            cpa16(dk, Kg); cpa16(dk + 4, Kg + 4);
            cpa16(dv, Vg); cpa16(dv + 4, Vg + 4);
            char* dm = Msb + st * 8192 + qlr * 64 + (t & 3) * 16;
            const unsigned char* mg = Mb + (size_t)qlr * S_ + kc + 64 + (t & 3) * 16;
            cpa16(dm, mg);
            cpa_commit();
        }
        const float* Ks = Ksb + (ic & 1) * (64 * AST);
        const float* Vs = Vsb + (ic & 1) * (64 * VST);
        const char*  Ms = Msb + (ic & 1) * 8192;

        // ---- QK: warp tile 32q x 16k
        float4 s[2][2];
#pragma unroll
        for (int i = 0; i < 2; i++)
#pragma unroll
            for (int j = 0; j < 2; j++) s[i][j] = make_float4(0.f, 0.f, 0.f, 0.f);
#pragma unroll
        for (int ks = 0; ks < 8; ks++) {
            const int kd = ks * 8;
            uint32_t bf[2][2];
#pragma unroll
            for (int j = 0; j < 2; j++) {
                const int n0 = 16 * wn + 8 * j + g;
                bf[j][0] = uf(Ks[n0 * AST + kd + tig]);
                bf[j][1] = uf(Ks[n0 * AST + kd + tig + 4]);
            }
#pragma unroll
            for (int i = 0; i < 2; i++)
#pragma unroll
                for (int j = 0; j < 2; j++) mma8(s[i][j], qa[i][ks], bf[j]);
        }

        // ---- exp + mask, normalized; p -> gmem attn; tf32r(p) -> Ps
#pragma unroll
        for (int i = 0; i < 2; i++) {
            const int r = 32 * wq + 16 * i + g;
            const float iv0 = inv[i][0], iv1 = inv[i][1];
#pragma unroll
            for (int j = 0; j < 2; j++) {
                const int c0 = 16 * wn + 8 * j + 2 * tig;
                float p0 = Ms[r * 64 + c0]           ? 0.f : __expf(s[i][j].x) * iv0;
                float p1 = Ms[r * 64 + c0 + 1]       ? 0.f : __expf(s[i][j].y) * iv0;
                float p2 = Ms[(r + 8) * 64 + c0]     ? 0.f : __expf(s[i][j].z) * iv1;
                float p3 = Ms[(r + 8) * 64 + c0 + 1] ? 0.f : __expf(s[i][j].w) * iv1;
                *(float2*)(attn_out + (attn_row0 + r) * S_ + kc + c0)     = make_float2(p0, p1);
                *(float2*)(attn_out + (attn_row0 + r + 8) * S_ + kc + c0) = make_float2(p2, p3);
                Ps[r * AST + c0]           = tf32r(p0);
                Ps[r * AST + c0 + 1]       = tf32r(p1);
                Ps[(r + 8) * AST + c0]     = tf32r(p2);
                Ps[(r + 8) * AST + c0 + 1] = tf32r(p3);
            }
        }
        __syncthreads();

        // ---- PV (normalized accumulate)
#pragma unroll
        for (int ks = 0; ks < 8; ks++) {
            const int kd = ks * 8;
            uint32_t pa[2][4], vb[2][2];
#pragma unroll
            for (int i = 0; i < 2; i++) {
                const int r = 32 * wq + 16 * i + g;
                pa[i][0] = uf(Ps[r * AST + kd + tig]);
                pa[i][1] = uf(Ps[(r + 8) * AST + kd + tig]);
                pa[i][2] = uf(Ps[r * AST + kd + tig + 4]);
                pa[i][3] = uf(Ps[(r + 8) * AST + kd + tig + 4]);
            }
#pragma unroll
            for (int j = 0; j < 2; j++) {
                const int d0 = 16 * wn + 8 * j + g;
                vb[j][0] = uf(Vs[(kd + tig) * VST + d0]);
                vb[j][1] = uf(Vs[(kd + tig + 4) * VST + d0]);
            }
#pragma unroll
            for (int i = 0; i < 2; i++)
#pragma unroll
                for (int j = 0; j < 2; j++) mma8(o[i][j], pa[i], vb[j]);
        }
    }

    // ---- ctx epilogue: already normalized; tf32-round, coalesced store
    __syncthreads();
#pragma unroll
    for (int i = 0; i < 2; i++) {
        const int r = 32 * wq + 16 * i + g;
#pragma unroll
        for (int j = 0; j < 2; j++) {
            const int c0 = 16 * wn + 8 * j + 2 * tig;
            Ps[r * AST + c0]           = tf32r(o[i][j].x);
            Ps[r * AST + c0 + 1]       = tf32r(o[i][j].y);
            Ps[(r + 8) * AST + c0]     = tf32r(o[i][j].z);
            Ps[(r + 8) * AST + c0 + 1] = tf32r(o[i][j].w);
        }
    }
    __syncthreads();
    {
        float* cg = g_ctx + (qrowg + qlr) * D_ + h * DK_ + qseg;
        const float* src = &Ps[qlr * AST + qseg];
#pragma unroll
        for (int jj = 0; jj < 4; jj++)
            *(float4*)(cg + 4 * jj) = *(const float4*)(src + 4 * jj);
    }
}

// ---------------- layernorm --------------------------------------------------
__global__ __launch_bounds__(256) void ln_kernel(
    const float* __restrict__ X, const float* __restrict__ gamma,
    const float* __restrict__ beta, float* __restrict__ out)
{
    const int r = blockIdx.x;
    const int t = threadIdx.x;
    float4 v = *(const float4*)&X[(size_t)r * D_ + t * 4];
    float s  = v.x + v.y + v.z + v.w;
    float sq = v.x * v.x + v.y * v.y + v.z * v.z + v.w * v.w;
#pragma unroll
    for (int o = 16; o > 0; o >>= 1) {
        s  += __shfl_xor_sync(0xFFFFFFFFu, s, o);
        sq += __shfl_xor_sync(0xFFFFFFFFu, sq, o);
    }
    __shared__ float ws[8], wqv[8];
    const int w = t >> 5;
    if ((t & 31) == 0) { ws[w] = s; wqv[w] = sq; }
    __syncthreads();
    if (t < 32) {
        float a  = (t < 8) ? ws[t] : 0.0f;
        float b2 = (t < 8) ? wqv[t] : 0.0f;
#pragma unroll
        for (int o = 4; o > 0; o >>= 1) {
            a  += __shfl_xor_sync(0xFFFFFFFFu, a, o);
            b2 += __shfl_xor_sync(0xFFFFFFFFu, b2, o);
        }
        if (t == 0) { ws[0] = a; wqv[0] = b2; }
    }
    __syncthreads();
    const float mean = ws[0] * (1.0f / D_);
    const float var  = wqv[0] * (1.0f / D_) - mean * mean;
    const float rstd = rsqrtf(var + LN_EPS_);
    float4 gm = *(const float4*)&gamma[t * 4];
    float4 be = *(const float4*)&beta[t * 4];
    float4 o4;
    o4.x = gm.x * (v.x - mean) * rstd + be.x;
    o4.y = gm.y * (v.y - mean) * rstd + be.y;
    o4.z = gm.z * (v.z - mean) * rstd + be.z;
    o4.w = gm.w * (v.w - mean) * rstd + be.w;
    *(float4*)&out[(size_t)r * D_ + t * 4] = o4;
}

// ---------------- launch -----------------------------------------------------
extern "C" void kernel_launch(void* const* d_in, const int* in_sizes, int n_in,
                              void* d_out, int out_size)
{
    (void)in_sizes; (void)n_in; (void)out_size;
    const float* query = (const float*)d_in[0];
    const float* key   = (const float*)d_in[1];
    const float* value = (const float*)d_in[2];
    const void*  mask  = d_in[3];
    const float* Wq = (const float*)d_in[4];
    const float* bq = (const float*)d_in[5];
    const float* Wk = (const float*)d_in[6];
    const float* bk = (const float*)d_in[7];
    const float* Wv = (const float*)d_in[8];
    const float* bv = (const float*)d_in[9];
    const float* Wo = (const float*)d_in[10];
    const float* bo = (const float*)d_in[11];
    const float* gamma = (const float*)d_in[12];
    const float* beta  = (const float*)d_in[13];

    float* out  = (float*)d_out;
    float* attn = out + BSD;

    float* gQ;   cudaGetSymbolAddress((void**)&gQ,   g_Q);
    float* gK;   cudaGetSymbolAddress((void**)&gK,   g_K);
    float* gV;   cudaGetSymbolAddress((void**)&gV,   g_V);
    float* gCtx; cudaGetSymbolAddress((void**)&gCtx, g_ctx);
    float* gOut; cudaGetSymbolAddress((void**)&gOut, g_out);
    float* gWr;  cudaGetSymbolAddress((void**)&gWr,  g_Wr);

    cudaFuncSetAttribute(gemm_tc, cudaFuncAttributeMaxDynamicSharedMemorySize, GEMM_SMEM_BYTES);
    cudaFuncSetAttribute(attn_sums, cudaFuncAttributeMaxDynamicSharedMemorySize, SUMS_SMEM_BYTES);
    cudaFuncSetAttribute(attn_tc, cudaFuncAttributeMaxDynamicSharedMemorySize, ATTN_SMEM_BYTES);

    detect_mask_kernel<<<1, 256>>>((const unsigned int*)mask);
    convert_mask_kernel<<<4096, 256>>>(mask);

    const size_t nW4 = (size_t)D_ * D_ / 4;   // 262144
    const size_t nX4 = BSD / 4;               // 2097152
    dim3 gg(GN / 128, GM / 128);

    // Q = round(query) @ round(Wq)^T + bq   (output tf32-rounded)
    round_copy<<<1024, 256>>>(Wq, gWr, nW4);
    round_copy<<<2048, 256>>>(query, gCtx, nX4);
    gemm_tc<<<gg, 256, GEMM_SMEM_BYTES>>>(gCtx, gWr, bq, nullptr, gQ, 1);
    // K
    round_copy<<<1024, 256>>>(Wk, gWr, nW4);
    round_copy<<<2048, 256>>>(key, gCtx, nX4);
    gemm_tc<<<gg, 256, GEMM_SMEM_BYTES>>>(gCtx, gWr, bk, nullptr, gK, 1);
    // V
    round_copy<<<1024, 256>>>(Wv, gWr, nW4);
    round_copy<<<2048, 256>>>(value, gCtx, nX4);
    gemm_tc<<<gg, 256, GEMM_SMEM_BYTES>>>(gCtx, gWr, bv, nullptr, gV, 1);

    attn_sums<<<dim3(S_ / 128, H_, B_), STH, SUMS_SMEM_BYTES>>>();
    attn_tc<<<dim3(S_ / 128, H_, B_), ATH, ATTN_SMEM_BYTES>>>(attn);

    // out-proj: ctx (already tf32) @ round(Wo)^T + bo + query
    round_copy<<<1024, 256>>>(Wo, gWr, nW4);
    gemm_tc<<<gg, 256, GEMM_SMEM_BYTES>>>(gCtx, gWr, bo, query, gOut, 0);

    ln_kernel<<<B_ * S_, 256>>>(gOut, gamma, beta, out);
}

// round 15
// speedup vs baseline: 1.0022x; 1.0022x over previous
#include <cuda_runtime.h>
#include <cstdint>

#define B_  4
#define S_  2048
#define D_  1024
#define H_  16
#define DK_ 64
#define SCALE_ 0.125f          // 1/sqrt(64), exact power of two
#define LN_EPS_ 1e-5f

#define GM 8192                // B_*S_
#define GN 1024
#define GK 1024

#define BSD ((size_t)B_ * S_ * D_)            // 8,388,608
#define NMASK ((size_t)B_ * S_ * S_)          // 16,777,216
#define NATTN ((size_t)B_ * H_ * S_ * S_)     // 268,435,456

// ---------------- device scratch --------------------------------------------
__device__ float g_Q[BSD];
__device__ float g_K[BSD];
__device__ float g_V[BSD];
__device__ float g_ctx[BSD];
__device__ float g_out[BSD];
__device__ float g_Wr[(size_t)D_ * D_];
__device__ float g_inv[(size_t)B_ * H_ * S_];
__device__ unsigned char g_mask[NMASK];
__device__ int g_mask_mode;

// ---------------- helpers ----------------------------------------------------
__device__ __forceinline__ float tf32r(float x) {
    uint32_t u; asm("cvt.rna.tf32.f32 %0, %1;" : "=r"(u) : "f"(x));
    return __uint_as_float(u);
}
__device__ __forceinline__ uint32_t uf(float x) { return __float_as_uint(x); }

__device__ __forceinline__ void mma8(float4& d, const uint32_t a[4], const uint32_t b[2]) {
    asm volatile(
        "mma.sync.aligned.m16n8k8.row.col.f32.tf32.tf32.f32 "
        "{%0,%1,%2,%3}, {%4,%5,%6,%7}, {%8,%9}, {%0,%1,%2,%3};"
        : "+f"(d.x), "+f"(d.y), "+f"(d.z), "+f"(d.w)
        : "r"(a[0]), "r"(a[1]), "r"(a[2]), "r"(a[3]), "r"(b[0]), "r"(b[1]));
}

__device__ __forceinline__ void cpa16(void* s, const void* g) {
    uint32_t sa = (uint32_t)__cvta_generic_to_shared(s);
    asm volatile("cp.async.cg.shared.global [%0], [%1], 16;" :: "r"(sa), "l"(g));
}
__device__ __forceinline__ void cpa_commit() { asm volatile("cp.async.commit_group;"); }
__device__ __forceinline__ void cpa_wait0()  { asm volatile("cp.async.wait_group 0;"); }
__device__ __forceinline__ void cpa_wait1()  { asm volatile("cp.async.wait_group 1;"); }

// ---------------- tf32 pre-round (RNA) ---------------------------------------
__global__ __launch_bounds__(256) void round_copy(const float* __restrict__ src,
                                                  float* __restrict__ dst, size_t n4)
{
    const size_t stride = (size_t)gridDim.x * blockDim.x;
    const float4* s4 = (const float4*)src;
    float4* d4 = (float4*)dst;
    for (size_t i = (size_t)blockIdx.x * blockDim.x + threadIdx.x; i < n4; i += stride) {
        float4 v = s4[i];
        d4[i] = make_float4(tf32r(v.x), tf32r(v.y), tf32r(v.z), tf32r(v.w));
    }
}

// ---------------- mask dtype detection --------------------------------------
__global__ void detect_mask_kernel(const unsigned int* __restrict__ w) {
    __shared__ unsigned int sh;
    if (threadIdx.x == 0) sh = 0u;
    __syncthreads();
    unsigned int acc = 0u;
    for (int i = threadIdx.x; i < 65536; i += 256) acc |= w[i];
    atomicOr(&sh, acc);
    __syncthreads();
    if (threadIdx.x == 0) {
        unsigned int o = sh;
        int mode;
        if (o & 0x0000FF00u)              mode = 0; // uint8 bools
        else if ((o & 0xFFFFFF00u) == 0u) mode = 1; // int32 0/1
        else                              mode = 2; // float32 0/1
        g_mask_mode = mode;
    }
}

__global__ void convert_mask_kernel(const void* __restrict__ mptr) {
    const int mode = g_mask_mode;
    const size_t n = NMASK;
    const size_t stride = (size_t)gridDim.x * blockDim.x;
    for (size_t i = (size_t)blockIdx.x * blockDim.x + threadIdx.x; i < n; i += stride) {
        unsigned char v;
        if (mode == 0)      v = ((const unsigned char*)mptr)[i];
        else if (mode == 1) v = (unsigned char)(((const int*)mptr)[i] != 0);
        else                v = (unsigned char)(((const float*)mptr)[i] != 0.0f);
        g_mask[i] = v;
    }
}

// ---------------- tf32 TC GEMM, cp.async 3-stage pipeline --------------------
// C = A @ W^T + bias (+resid). A,W pre-rounded tf32. Block 128x128, kc=32.
// 8 warps = 4m x 2n, warp tile 32x64. 3-stage circular buffer: wait_group<=1
// gives each tile load ~2 compute iterations to land.
#define SA 36
#define STG_F (128 * SA)                          // floats per stage per array
#define GEMM_SMEM_BYTES (3 * 2 * STG_F * 4)       // 110592
__global__ __launch_bounds__(256, 2) void gemm_tc(
    const float* __restrict__ A, const float* __restrict__ W,
    const float* __restrict__ bias, const float* __restrict__ resid,
    float* __restrict__ C, int round_out)
{
    extern __shared__ float gsm[];
    float* Asb = gsm;                      // 3 stages x STG_F
    float* Wsb = gsm + 3 * STG_F;
    const int t = threadIdx.x;
    const int lane = t & 31, w = t >> 5;
    const int g = lane >> 2, tig = lane & 3;
    const int wq = w >> 1, wn = w & 1;
    const int bm = blockIdx.y * 128, bn = blockIdx.x * 128;
    const int lrow = t >> 1, lseg = (t & 1) * 16;

    const float* Ag = A + (size_t)(bm + lrow) * GK + lseg;
    const float* Wg = W + (size_t)(bn + lrow) * GK + lseg;

    float4 acc[2][8];
#pragma unroll
    for (int i = 0; i < 2; i++)
#pragma unroll
        for (int j = 0; j < 8; j++) acc[i][j] = make_float4(0.f, 0.f, 0.f, 0.f);

    // preload stages 0 and 1
#pragma unroll
    for (int s = 0; s < 2; s++) {
        float* da = Asb + s * STG_F + lrow * SA + lseg;
        float* dw = Wsb + s * STG_F + lrow * SA + lseg;
        const int k0 = s * 32;
#pragma unroll
        for (int p = 0; p < 4; p++) { cpa16(da + 4 * p, Ag + k0 + 4 * p); cpa16(dw + 4 * p, Wg + k0 + 4 * p); }
        cpa_commit();
    }

    int stc = 0;   // compute stage
    int stl = 2;   // next load stage
    for (int it = 0; it < GK / 32; it++) {
        cpa_wait1();          // stage `it` resident (<=1 group pending)
        __syncthreads();
        if (it + 2 < GK / 32) {
            const int k0 = (it + 2) * 32;
            float* da = Asb + stl * STG_F + lrow * SA + lseg;
            float* dw = Wsb + stl * STG_F + lrow * SA + lseg;
#pragma unroll
            for (int p = 0; p < 4; p++) { cpa16(da + 4 * p, Ag + k0 + 4 * p); cpa16(dw + 4 * p, Wg + k0 + 4 * p); }
            cpa_commit();
            if (++stl == 3) stl = 0;
        } else {
            cpa_commit();     // keep group count in step for wait_group 1
        }
        const float* as = Asb + stc * STG_F;
        const float* ws = Wsb + stc * STG_F;
        if (++stc == 3) stc = 0;
#pragma unroll
        for (int ks = 0; ks < 4; ks++) {
            const int kc = ks * 8;
            uint32_t a[2][4], bfr[8][2];
#pragma unroll
            for (int i = 0; i < 2; i++) {
                const int r = 32 * wq + 16 * i + g;
                a[i][0] = uf(as[r * SA + kc + tig]);
                a[i][1] = uf(as[(r + 8) * SA + kc + tig]);
                a[i][2] = uf(as[r * SA + kc + tig + 4]);
                a[i][3] = uf(as[(r + 8) * SA + kc + tig + 4]);
            }
#pragma unroll
            for (int j = 0; j < 8; j++) {
                const int n0 = 64 * wn + 8 * j + g;
                bfr[j][0] = uf(ws[n0 * SA + kc + tig]);
                bfr[j][1] = uf(ws[n0 * SA + kc + tig + 4]);
            }
#pragma unroll
            for (int i = 0; i < 2; i++)
#pragma unroll
                for (int j = 0; j < 8; j++) mma8(acc[i][j], a[i], bfr[j]);
        }
    }
#pragma unroll
    for (int i = 0; i < 2; i++) {
        const int r0 = bm + 32 * wq + 16 * i + g;
#pragma unroll
        for (int j = 0; j < 8; j++) {
            const int cg = bn + 64 * wn + 8 * j + 2 * tig;
            float2 bb = *(const float2*)&bias[cg];
            float2 o0 = make_float2(acc[i][j].x + bb.x, acc[i][j].y + bb.y);
            float2 o1 = make_float2(acc[i][j].z + bb.x, acc[i][j].w + bb.y);
            if (resid) {
                float2 ra = *(const float2*)&resid[(size_t)r0 * GN + cg];
                float2 rb = *(const float2*)&resid[(size_t)(r0 + 8) * GN + cg];
                o0.x += ra.x; o0.y += ra.y; o1.x += rb.x; o1.y += rb.y;
            }
            if (round_out) {
                o0.x = tf32r(o0.x); o0.y = tf32r(o0.y);
                o1.x = tf32r(o1.x); o1.y = tf32r(o1.y);
            }
            *(float2*)&C[(size_t)r0 * GN + cg] = o0;
            *(float2*)&C[(size_t)(r0 + 8) * GN + cg] = o1;
        }
    }
}

// ---------------- single-pass TC attention, 512 threads (16 warps) -----------
// qtile=128, ktile=64. Warp grid 4q x 4k; warp tile 32x16. Q frags in regs.
// Writes UNNORMALIZED exp to attn (sector-aligned float2 stores), rowsum inv
// to g_inv, tf32-rounded normalized ctx to g_ctx.
#define ATH 512
#define AST 68   // Q/K/P stride (272B, 16B-aligned)
#define VST 72   // V stride (288B)
#define OFF_KS  8704                       // Ps = 128*AST = 8704 floats
#define OFF_VS  (OFF_KS + 2 * 64 * AST)    // 17408
#define OFF_RED (OFF_VS + 2 * 64 * VST)    // 26624
#define OFF_INV (OFF_RED + 128 * 16)       // 28672
#define OFF_MS  (OFF_INV + 128)            // 28800 floats; then 2*8192 mask bytes
#define ATTN_SMEM_BYTES (OFF_MS * 4 + 2 * 8192)   // 131584
__global__ __launch_bounds__(ATH) void attn_tc(float* __restrict__ attn_out)
{
    extern __shared__ float sm[];
    float* Ps   = sm;
    float* Ksb  = sm + OFF_KS;
    float* Vsb  = sm + OFF_VS;
    float* red  = sm + OFF_RED;
    float* invs = sm + OFF_INV;
    char*  Msb  = (char*)(sm + OFF_MS);

    const int t = threadIdx.x;
    const int lane = t & 31, w = t >> 5;
    const int g = lane >> 2, tig = lane & 3;
    const int wq = w >> 2, wn = w & 3;            // 4q x 4k warp grid
    const int qt = blockIdx.x, h = blockIdx.y, b = blockIdx.z;
    const int qg0 = qt * 128;
    const size_t qrowg = (size_t)(b * S_) + qg0;
    const int qlr = t >> 2, qseg = (t & 3) * 16;  // 128-row staging (16 floats/thread)
    const int kr = t >> 3, kq = t & 7;            // 64-row staging (8 floats/thread)

    const float* Kb = g_K + (size_t)(b * S_) * D_ + h * DK_;
    const float* Vb = g_V + (size_t)(b * S_) * D_ + h * DK_;
    const unsigned char* Mb = g_mask + (size_t)(b * S_ + qg0) * S_;
    const size_t attn_row0 = (size_t)(h * B_ + b) * S_ + qg0;

    // stage Q (pre-rounded) into Ps, lift fragments with exact *0.125 scale
    {
        const float* Qg = g_Q + (qrowg + qlr) * D_ + h * DK_ + qseg;
        float* dst = &Ps[qlr * AST + qseg];
#pragma unroll
        for (int jj = 0; jj < 4; jj++)
            *(float4*)(dst + 4 * jj) = *(const float4*)(Qg + 4 * jj);
    }
    __syncthreads();
    uint32_t qa[2][8][4];
#pragma unroll
    for (int i = 0; i < 2; i++) {
        const int r = 32 * wq + 16 * i + g;
#pragma unroll
        for (int ks = 0; ks < 8; ks++) {
            const int kd = ks * 8;
            qa[i][ks][0] = uf(SCALE_ * Ps[r * AST + kd + tig]);
            qa[i][ks][1] = uf(SCALE_ * Ps[(r + 8) * AST + kd + tig]);
            qa[i][ks][2] = uf(SCALE_ * Ps[r * AST + kd + tig + 4]);
            qa[i][ks][3] = uf(SCALE_ * Ps[(r + 8) * AST + kd + tig + 4]);
        }
    }

    // preload stage 0 (kc = 0)
    {
        float* dk = Ksb + kr * AST + kq * 8;
        float* dv = Vsb + kr * VST + kq * 8;
        const float* Kg = Kb + (size_t)kr * D_ + kq * 8;
        const float* Vg = Vb + (size_t)kr * D_ + kq * 8;
        cpa16(dk, Kg); cpa16(dk + 4, Kg + 4);
        cpa16(dv, Vg); cpa16(dv + 4, Vg + 4);
        char* dm = Msb + qlr * 64 + (t & 3) * 16;
        const unsigned char* mg = Mb + (size_t)qlr * S_ + (t & 3) * 16;
        cpa16(dm, mg);
        cpa_commit();
    }

    float rs[2][2] = {{0.f, 0.f}, {0.f, 0.f}};
    float4 o[2][2];
#pragma unroll
    for (int i = 0; i < 2; i++)
#pragma unroll
        for (int j = 0; j < 2; j++) o[i][j] = make_float4(0.f, 0.f, 0.f, 0.f);

    for (int ic = 0; ic < S_ / 64; ic++) {
        const int kc = ic * 64;
        cpa_wait0();
        __syncthreads();
        if (ic + 1 < S_ / 64) {
            const int st = (ic + 1) & 1;
            float* dk = Ksb + st * (64 * AST) + kr * AST + kq * 8;
            float* dv = Vsb + st * (64 * VST) + kr * VST + kq * 8;
            const float* Kg = Kb + (size_t)(kc + 64 + kr) * D_ + kq * 8;
            const float* Vg = Vb + (size_t)(kc + 64 + kr) * D_ + kq * 8;
            cpa16(dk, Kg); cpa16(dk + 4, Kg + 4);
            cpa16(dv, Vg); cpa16(dv + 4, Vg + 4);
            char* dm = Msb + st * 8192 + qlr * 64 + (t & 3) * 16;
            const unsigned char* mg = Mb + (size_t)qlr * S_ + kc + 64 + (t & 3) * 16;
            cpa16(dm, mg);
            cpa_commit();
        }
        const float* Ks = Ksb + (ic & 1) * (64 * AST);
        const float* Vs = Vsb + (ic & 1) * (64 * VST);
        const char*  Ms = Msb + (ic & 1) * 8192;

        // ---- QK: warp tile 32q x 16k
        float4 s[2][2];
#pragma unroll
        for (int i = 0; i < 2; i++)
#pragma unroll
            for (int j = 0; j < 2; j++) s[i][j] = make_float4(0.f, 0.f, 0.f, 0.f);
#pragma unroll
        for (int ks = 0; ks < 8; ks++) {
            const int kd = ks * 8;
            uint32_t bf[2][2];
#pragma unroll
            for (int j = 0; j < 2; j++) {
                const int n0 = 16 * wn + 8 * j + g;
                bf[j][0] = uf(Ks[n0 * AST + kd + tig]);
                bf[j][1] = uf(Ks[n0 * AST + kd + tig + 4]);
            }
#pragma unroll
            for (int i = 0; i < 2; i++)
#pragma unroll
                for (int j = 0; j < 2; j++) mma8(s[i][j], qa[i][ks], bf[j]);
        }

        // ---- exp + mask + rowsum; raw p -> gmem attn; tf32r(p) -> Ps
#pragma unroll
        for (int i = 0; i < 2; i++) {
            const int r = 32 * wq + 16 * i + g;
#pragma unroll
            for (int j = 0; j < 2; j++) {
                const int c0 = 16 * wn + 8 * j + 2 * tig;
                float p0 = Ms[r * 64 + c0]           ? 0.f : __expf(s[i][j].x);
                float p1 = Ms[r * 64 + c0 + 1]       ? 0.f : __expf(s[i][j].y);
                float p2 = Ms[(r + 8) * 64 + c0]     ? 0.f : __expf(s[i][j].z);
                float p3 = Ms[(r + 8) * 64 + c0 + 1] ? 0.f : __expf(s[i][j].w);
                rs[i][0] += p0 + p1; rs[i][1] += p2 + p3;
                *(float2*)(attn_out + (attn_row0 + r) * S_ + kc + c0)     = make_float2(p0, p1);
                *(float2*)(attn_out + (attn_row0 + r + 8) * S_ + kc + c0) = make_float2(p2, p3);
                Ps[r * AST + c0]           = tf32r(p0);
                Ps[r * AST + c0 + 1]       = tf32r(p1);
                Ps[(r + 8) * AST + c0]     = tf32r(p2);
                Ps[(r + 8) * AST + c0 + 1] = tf32r(p3);
            }
        }
        __syncthreads();

        // ---- PV (unnormalized accumulate): warp covers d-range 16*wn..+15
#pragma unroll
        for (int ks = 0; ks < 8; ks++) {
            const int kd = ks * 8;
            uint32_t pa[2][4], vb[2][2];
#pragma unroll
            for (int i = 0; i < 2; i++) {
                const int r = 32 * wq + 16 * i + g;
                pa[i][0] = uf(Ps[r * AST + kd + tig]);
                pa[i][1] = uf(Ps[(r + 8) * AST + kd + tig]);
                pa[i][2] = uf(Ps[r * AST + kd + tig + 4]);
                pa[i][3] = uf(Ps[(r + 8) * AST + kd + tig + 4]);
            }
#pragma unroll
            for (int j = 0; j < 2; j++) {
                const int d0 = 16 * wn + 8 * j + g;
                vb[j][0] = uf(Vs[(kd + tig) * VST + d0]);
                vb[j][1] = uf(Vs[(kd + tig + 4) * VST + d0]);
            }
#pragma unroll
            for (int i = 0; i < 2; i++)
#pragma unroll
                for (int j = 0; j < 2; j++) mma8(o[i][j], pa[i], vb[j]);
        }
    }

    // ---- rowsum reduction -> inv, g_inv (16 partials per row: 4 wn x 4 tig)
    __syncthreads();
#pragma unroll
    for (int i = 0; i < 2; i++) {
        const int r = 32 * wq + 16 * i + g;
        red[r * 16 + wn * 4 + tig]       = rs[i][0];
        red[(r + 8) * 16 + wn * 4 + tig] = rs[i][1];
    }
    __syncthreads();
    if (t < 128) {
        float ssum = 0.f;
#pragma unroll
        for (int j = 0; j < 16; j++) ssum += red[t * 16 + j];
        const float iv = 1.0f / ssum;
        invs[t] = iv;
        g_inv[attn_row0 + t] = iv;
    }
    __syncthreads();

    // ---- ctx epilogue: normalized + tf32-rounded, staged for coalesced store
#pragma unroll
    for (int i = 0; i < 2; i++) {
        const int r = 32 * wq + 16 * i + g;
        const float iv0 = invs[r], iv1 = invs[r + 8];
#pragma unroll
        for (int j = 0; j < 2; j++) {
            const int c0 = 16 * wn + 8 * j + 2 * tig;
            Ps[r * AST + c0]           = tf32r(o[i][j].x * iv0);
            Ps[r * AST + c0 + 1]       = tf32r(o[i][j].y * iv0);
            Ps[(r + 8) * AST + c0]     = tf32r(o[i][j].z * iv1);
            Ps[(r + 8) * AST + c0 + 1] = tf32r(o[i][j].w * iv1);
        }
    }
    __syncthreads();
    {
        float* cg = g_ctx + (qrowg + qlr) * D_ + h * DK_ + qseg;
        const float* src = &Ps[qlr * AST + qseg];
#pragma unroll
        for (int jj = 0; jj < 4; jj++)
            *(float4*)(cg + 4 * jj) = *(const float4*)(src + 4 * jj);
    }
}

// ---------------- attn normalization: attn *= 1/rowsum, MLP=4 + streaming ----
__global__ __launch_bounds__(256) void norm_attn_kernel(float* __restrict__ attn)
{
    const size_t n4 = NATTN / 4;
    const size_t gs = (size_t)gridDim.x * blockDim.x;
    float4* p = (float4*)attn;
    size_t i = (size_t)blockIdx.x * blockDim.x + threadIdx.x;
    for (; i + 3 * gs < n4; i += 4 * gs) {
        const size_t i0 = i, i1 = i + gs, i2 = i + 2 * gs, i3 = i + 3 * gs;
        float4 v0 = __ldcs(p + i0);
        float4 v1 = __ldcs(p + i1);
        float4 v2 = __ldcs(p + i2);
        float4 v3 = __ldcs(p + i3);
        const float a0 = g_inv[i0 >> 9], a1 = g_inv[i1 >> 9];
        const float a2 = g_inv[i2 >> 9], a3 = g_inv[i3 >> 9];
        v0.x *= a0; v0.y *= a0; v0.z *= a0; v0.w *= a0;
        v1.x *= a1; v1.y *= a1; v1.z *= a1; v1.w *= a1;
        v2.x *= a2; v2.y *= a2; v2.z *= a2; v2.w *= a2;
        v3.x *= a3; v3.y *= a3; v3.z *= a3; v3.w *= a3;
        __stcs(p + i0, v0);
        __stcs(p + i1, v1);
        __stcs(p + i2, v2);
        __stcs(p + i3, v3);
    }
    for (; i < n4; i += gs) {
        const float a = g_inv[i >> 9];
        float4 v = __ldcs(p + i);
        v.x *= a; v.y *= a; v.z *= a; v.w *= a;
        __stcs(p + i, v);
    }
}

// ---------------- layernorm --------------------------------------------------
__global__ __launch_bounds__(256) void ln_kernel(
    const float* __restrict__ X, const float* __restrict__ gamma,
    const float* __restrict__ beta, float* __restrict__ out)
{
    const int r = blockIdx.x;
    const int t = threadIdx.x;
    float4 v = *(const float4*)&X[(size_t)r * D_ + t * 4];
    float s  = v.x + v.y + v.z + v.w;
    float sq = v.x * v.x + v.y * v.y + v.z * v.z + v.w * v.w;
#pragma unroll
    for (int o = 16; o > 0; o >>= 1) {
        s  += __shfl_xor_sync(0xFFFFFFFFu, s, o);
        sq += __shfl_xor_sync(0xFFFFFFFFu, sq, o);
    }
    __shared__ float ws[8], wqv[8];
    const int w = t >> 5;
    if ((t & 31) == 0) { ws[w] = s; wqv[w] = sq; }
    __syncthreads();
    if (t < 32) {
        float a  = (t < 8) ? ws[t] : 0.0f;
        float b2 = (t < 8) ? wqv[t] : 0.0f;
#pragma unroll
        for (int o = 4; o > 0; o >>= 1) {
            a  += __shfl_xor_sync(0xFFFFFFFFu, a, o);
            b2 += __shfl_xor_sync(0xFFFFFFFFu, b2, o);
        }
        if (t == 0) { ws[0] = a; wqv[0] = b2; }
    }
    __syncthreads();
    const float mean = ws[0] * (1.0f / D_);
    const float var  = wqv[0] * (1.0f / D_) - mean * mean;
    const float rstd = rsqrtf(var + LN_EPS_);
    float4 gm = *(const float4*)&gamma[t * 4];
    float4 be = *(const float4*)&beta[t * 4];
    float4 o4;
    o4.x = gm.x * (v.x - mean) * rstd + be.x;
    o4.y = gm.y * (v.y - mean) * rstd + be.y;
    o4.z = gm.z * (v.z - mean) * rstd + be.z;
    o4.w = gm.w * (v.w - mean) * rstd + be.w;
    *(float4*)&out[(size_t)r * D_ + t * 4] = o4;
}

// ---------------- launch -----------------------------------------------------
extern "C" void kernel_launch(void* const* d_in, const int* in_sizes, int n_in,
                              void* d_out, int out_size)
{
    (void)in_sizes; (void)n_in; (void)out_size;
    const float* query = (const float*)d_in[0];
    const float* key   = (const float*)d_in[1];
    const float* value = (const float*)d_in[2];
    const void*  mask  = d_in[3];
    const float* Wq = (const float*)d_in[4];
    const float* bq = (const float*)d_in[5];
    const float* Wk = (const float*)d_in[6];
    const float* bk = (const float*)d_in[7];
    const float* Wv = (const float*)d_in[8];
    const float* bv = (const float*)d_in[9];
    const float* Wo = (const float*)d_in[10];
    const float* bo = (const float*)d_in[11];
    const float* gamma = (const float*)d_in[12];
    const float* beta  = (const float*)d_in[13];

    float* out  = (float*)d_out;
    float* attn = out + BSD;

    float* gQ;   cudaGetSymbolAddress((void**)&gQ,   g_Q);
    float* gK;   cudaGetSymbolAddress((void**)&gK,   g_K);
    float* gV;   cudaGetSymbolAddress((void**)&gV,   g_V);
    float* gCtx; cudaGetSymbolAddress((void**)&gCtx, g_ctx);
    float* gOut; cudaGetSymbolAddress((void**)&gOut, g_out);
    float* gWr;  cudaGetSymbolAddress((void**)&gWr,  g_Wr);

    cudaFuncSetAttribute(gemm_tc, cudaFuncAttributeMaxDynamicSharedMemorySize, GEMM_SMEM_BYTES);
    cudaFuncSetAttribute(attn_tc, cudaFuncAttributeMaxDynamicSharedMemorySize, ATTN_SMEM_BYTES);

    detect_mask_kernel<<<1, 256>>>((const unsigned int*)mask);
    convert_mask_kernel<<<4096, 256>>>(mask);

    const size_t nW4 = (size_t)D_ * D_ / 4;   // 262144
    const size_t nX4 = BSD / 4;               // 2097152
    dim3 gg(GN / 128, GM / 128);

    // Q = round(query) @ round(Wq)^T + bq   (output tf32-rounded)
    round_copy<<<1024, 256>>>(Wq, gWr, nW4);
    round_copy<<<2048, 256>>>(query, gCtx, nX4);
    gemm_tc<<<gg, 256, GEMM_SMEM_BYTES>>>(gCtx, gWr, bq, nullptr, gQ, 1);
    // K
    round_copy<<<1024, 256>>>(Wk, gWr, nW4);
    round_copy<<<2048, 256>>>(key, gCtx, nX4);
    gemm_tc<<<gg, 256, GEMM_SMEM_BYTES>>>(gCtx, gWr, bk, nullptr, gK, 1);
    // V
    round_copy<<<1024, 256>>>(Wv, gWr, nW4);
    round_copy<<<2048, 256>>>(value, gCtx, nX4);
    gemm_tc<<<gg, 256, GEMM_SMEM_BYTES>>>(gCtx, gWr, bv, nullptr, gV, 1);

    attn_tc<<<dim3(S_ / 128, H_, B_), ATH, ATTN_SMEM_BYTES>>>(attn);

    // out-proj: ctx (already tf32) @ round(Wo)^T + bo + query
    round_copy<<<1024, 256>>>(Wo, gWr, nW4);
    gemm_tc<<<gg, 256, GEMM_SMEM_BYTES>>>(gCtx, gWr, bo, query, gOut, 0);

    norm_attn_kernel<<<16384, 256>>>(attn);
    ln_kernel<<<B_ * S_, 256>>>(gOut, gamma, beta, out);
}

// round 16
// speedup vs baseline: 1.0452x; 1.0429x over previous
#include <cuda_runtime.h>
#include <cstdint>

#define B_  4
#define S_  2048
#define D_  1024
#define H_  16
#define DK_ 64
#define SCALE_ 0.125f          // 1/sqrt(64), exact power of two
#define LN_EPS_ 1e-5f

#define GM 8192                // B_*S_
#define GN 1024
#define GK 1024

#define BSD ((size_t)B_ * S_ * D_)            // 8,388,608
#define NW  ((size_t)D_ * D_)                 // 1,048,576
#define NMASK ((size_t)B_ * S_ * S_)          // 16,777,216
#define NATTN ((size_t)B_ * H_ * S_ * S_)     // 268,435,456

// ---------------- device scratch --------------------------------------------
__device__ float g_Q[BSD];
__device__ float g_K[BSD];
__device__ float g_V[BSD];
__device__ float g_ctx[BSD];
__device__ float g_out[BSD];
__device__ float g_Xq[BSD];
__device__ float g_Xk[BSD];
__device__ float g_Xv[BSD];
__device__ float g_Wq[NW];
__device__ float g_Wk[NW];
__device__ float g_Wv[NW];
__device__ float g_Wo[NW];
__device__ float g_inv[(size_t)B_ * H_ * S_];
__device__ unsigned char g_mask[NMASK];
__device__ int g_mask_mode;

// ---------------- helpers ----------------------------------------------------
__device__ __forceinline__ float tf32r(float x) {
    uint32_t u; asm("cvt.rna.tf32.f32 %0, %1;" : "=r"(u) : "f"(x));
    return __uint_as_float(u);
}
__device__ __forceinline__ uint32_t uf(float x) { return __float_as_uint(x); }

__device__ __forceinline__ void mma8(float4& d, const uint32_t a[4], const uint32_t b[2]) {
    asm volatile(
        "mma.sync.aligned.m16n8k8.row.col.f32.tf32.tf32.f32 "
        "{%0,%1,%2,%3}, {%4,%5,%6,%7}, {%8,%9}, {%0,%1,%2,%3};"
        : "+f"(d.x), "+f"(d.y), "+f"(d.z), "+f"(d.w)
        : "r"(a[0]), "r"(a[1]), "r"(a[2]), "r"(a[3]), "r"(b[0]), "r"(b[1]));
}

__device__ __forceinline__ void cpa16(void* s, const void* g) {
    uint32_t sa = (uint32_t)__cvta_generic_to_shared(s);
    asm volatile("cp.async.cg.shared.global [%0], [%1], 16;" :: "r"(sa), "l"(g));
}
__device__ __forceinline__ void cpa_commit() { asm volatile("cp.async.commit_group;"); }
__device__ __forceinline__ void cpa_wait0()  { asm volatile("cp.async.wait_group 0;"); }

// ---------------- fused tf32 pre-round (RNA): 7 segments in one launch -------
__global__ __launch_bounds__(256) void round_all(
    const float* __restrict__ query, const float* __restrict__ key,
    const float* __restrict__ value, const float* __restrict__ Wq,
    const float* __restrict__ Wk, const float* __restrict__ Wv,
    const float* __restrict__ Wo)
{
    const int seg = blockIdx.y;
    const float* src; float* dst; size_t n4;
    switch (seg) {
        case 0: src = query; dst = g_Xq; n4 = BSD / 4; break;
        case 1: src = key;   dst = g_Xk; n4 = BSD / 4; break;
        case 2: src = value; dst = g_Xv; n4 = BSD / 4; break;
        case 3: src = Wq;    dst = g_Wq; n4 = NW / 4;  break;
        case 4: src = Wk;    dst = g_Wk; n4 = NW / 4;  break;
        case 5: src = Wv;    dst = g_Wv; n4 = NW / 4;  break;
        default: src = Wo;   dst = g_Wo; n4 = NW / 4;  break;
    }
    const size_t stride = (size_t)gridDim.x * blockDim.x;
    const float4* s4 = (const float4*)src;
    float4* d4 = (float4*)dst;
    for (size_t i = (size_t)blockIdx.x * blockDim.x + threadIdx.x; i < n4; i += stride) {
        float4 v = s4[i];
        d4[i] = make_float4(tf32r(v.x), tf32r(v.y), tf32r(v.z), tf32r(v.w));
    }
}

// ---------------- mask dtype detection --------------------------------------
__global__ void detect_mask_kernel(const unsigned int* __restrict__ w) {
    __shared__ unsigned int sh;
    if (threadIdx.x == 0) sh = 0u;
    __syncthreads();
    unsigned int acc = 0u;
    for (int i = threadIdx.x; i < 65536; i += 256) acc |= w[i];
    atomicOr(&sh, acc);
    __syncthreads();
    if (threadIdx.x == 0) {
        unsigned int o = sh;
        int mode;
        if (o & 0x0000FF00u)              mode = 0; // uint8 bools
        else if ((o & 0xFFFFFF00u) == 0u) mode = 1; // int32 0/1
        else                              mode = 2; // float32 0/1
        g_mask_mode = mode;
    }
}

__global__ void convert_mask_kernel(const void* __restrict__ mptr) {
    const int mode = g_mask_mode;
    const size_t n = NMASK;
    const size_t stride = (size_t)gridDim.x * blockDim.x;
    for (size_t i = (size_t)blockIdx.x * blockDim.x + threadIdx.x; i < n; i += stride) {
        unsigned char v;
        if (mode == 0)      v = ((const unsigned char*)mptr)[i];
        else if (mode == 1) v = (unsigned char)(((const int*)mptr)[i] != 0);
        else                v = (unsigned char)(((const float*)mptr)[i] != 0.0f);
        g_mask[i] = v;
    }
}

// ---------------- tf32 TC GEMM body, cp.async double-buffered ----------------
// C = A @ W^T + bias (+resid). A,W pre-rounded tf32. Block 128x128, kc=32.
// 8 warps = 4m x 2n, warp tile 32x64.
#define SA 36
#define GEMM_SMEM_BYTES (2 * 2 * 128 * SA * 4)   // 73728
__device__ __forceinline__ void gemm_body(
    const float* __restrict__ A, const float* __restrict__ W,
    const float* __restrict__ bias, const float* __restrict__ resid,
    float* __restrict__ C, int round_out, int bx, int by, float* gsm)
{
    float* Asb = gsm;                      // 2 stages x 128*SA
    float* Wsb = gsm + 2 * 128 * SA;
    const int t = threadIdx.x;
    const int lane = t & 31, w = t >> 5;
    const int g = lane >> 2, tig = lane & 3;
    const int wq = w >> 1, wn = w & 1;
    const int bm = by * 128, bn = bx * 128;
    const int lrow = t >> 1, lseg = (t & 1) * 16;

    const float* Ag = A + (size_t)(bm + lrow) * GK + lseg;
    const float* Wg = W + (size_t)(bn + lrow) * GK + lseg;

    float4 acc[2][8];
#pragma unroll
    for (int i = 0; i < 2; i++)
#pragma unroll
        for (int j = 0; j < 8; j++) acc[i][j] = make_float4(0.f, 0.f, 0.f, 0.f);

    // preload stage 0
    {
        float* da = Asb + lrow * SA + lseg;
        float* dw = Wsb + lrow * SA + lseg;
#pragma unroll
        for (int p = 0; p < 4; p++) { cpa16(da + 4 * p, Ag + 4 * p); cpa16(dw + 4 * p, Wg + 4 * p); }
        cpa_commit();
    }

    for (int it = 0; it < GK / 32; it++) {
        cpa_wait0();
        __syncthreads();
        if (it + 1 < GK / 32) {
            const int k0 = (it + 1) * 32;
            const int st = (it + 1) & 1;
            float* da = Asb + st * (128 * SA) + lrow * SA + lseg;
            float* dw = Wsb + st * (128 * SA) + lrow * SA + lseg;
#pragma unroll
            for (int p = 0; p < 4; p++) { cpa16(da + 4 * p, Ag + k0 + 4 * p); cpa16(dw + 4 * p, Wg + k0 + 4 * p); }
            cpa_commit();
        }
        const float* as = Asb + (it & 1) * (128 * SA);
        const float* ws = Wsb + (it & 1) * (128 * SA);
#pragma unroll
        for (int ks = 0; ks < 4; ks++) {
            const int kc = ks * 8;
            uint32_t a[2][4], bfr[8][2];
#pragma unroll
            for (int i = 0; i < 2; i++) {
                const int r = 32 * wq + 16 * i + g;
                a[i][0] = uf(as[r * SA + kc + tig]);
                a[i][1] = uf(as[(r + 8) * SA + kc + tig]);
                a[i][2] = uf(as[r * SA + kc + tig + 4]);
                a[i][3] = uf(as[(r + 8) * SA + kc + tig + 4]);
            }
#pragma unroll
            for (int j = 0; j < 8; j++) {
                const int n0 = 64 * wn + 8 * j + g;
                bfr[j][0] = uf(ws[n0 * SA + kc + tig]);
                bfr[j][1] = uf(ws[n0 * SA + kc + tig + 4]);
            }
#pragma unroll
            for (int i = 0; i < 2; i++)
#pragma unroll
                for (int j = 0; j < 8; j++) mma8(acc[i][j], a[i], bfr[j]);
        }
    }
#pragma unroll
    for (int i = 0; i < 2; i++) {
        const int r0 = bm + 32 * wq + 16 * i + g;
#pragma unroll
        for (int j = 0; j < 8; j++) {
            const int cg = bn + 64 * wn + 8 * j + 2 * tig;
            float2 bb = *(const float2*)&bias[cg];
            float2 o0 = make_float2(acc[i][j].x + bb.x, acc[i][j].y + bb.y);
            float2 o1 = make_float2(acc[i][j].z + bb.x, acc[i][j].w + bb.y);
            if (resid) {
                float2 ra = *(const float2*)&resid[(size_t)r0 * GN + cg];
                float2 rb = *(const float2*)&resid[(size_t)(r0 + 8) * GN + cg];
                o0.x += ra.x; o0.y += ra.y; o1.x += rb.x; o1.y += rb.y;
            }
            if (round_out) {
                o0.x = tf32r(o0.x); o0.y = tf32r(o0.y);
                o1.x = tf32r(o1.x); o1.y = tf32r(o1.y);
            }
            *(float2*)&C[(size_t)r0 * GN + cg] = o0;
            *(float2*)&C[(size_t)(r0 + 8) * GN + cg] = o1;
        }
    }
}

__global__ __launch_bounds__(256, 2) void gemm_tc(
    const float* __restrict__ A, const float* __restrict__ W,
    const float* __restrict__ bias, const float* __restrict__ resid,
    float* __restrict__ C, int round_out)
{
    extern __shared__ float gsm[];
    gemm_body(A, W, bias, resid, C, round_out, blockIdx.x, blockIdx.y, gsm);
}

// fused Q/K/V projections: grid.z selects the triple
__global__ __launch_bounds__(256, 2) void gemm_qkv(
    const float* __restrict__ bq, const float* __restrict__ bk,
    const float* __restrict__ bv)
{
    extern __shared__ float gsm[];
    const int z = blockIdx.z;
    const float* A    = (z == 0) ? g_Xq : (z == 1) ? g_Xk : g_Xv;
    const float* W    = (z == 0) ? g_Wq : (z == 1) ? g_Wk : g_Wv;
    const float* bias = (z == 0) ? bq   : (z == 1) ? bk   : bv;
    float* C          = (z == 0) ? g_Q  : (z == 1) ? g_K  : g_V;
    gemm_body(A, W, bias, nullptr, C, 1, blockIdx.x, blockIdx.y, gsm);
}

// ---------------- single-pass TC attention, 512 threads (16 warps) -----------
// qtile=128, ktile=64. Warp grid 4q x 4k; warp tile 32x16. Q frags in regs.
// Writes UNNORMALIZED exp to attn (sector-aligned float2 stores), rowsum inv
// to g_inv, tf32-rounded normalized ctx to g_ctx.
#define ATH 512
#define AST 68   // Q/K/P stride (272B, 16B-aligned)
#define VST 72   // V stride (288B)
#define OFF_KS  8704                       // Ps = 128*AST = 8704 floats
#define OFF_VS  (OFF_KS + 2 * 64 * AST)    // 17408
#define OFF_RED (OFF_VS + 2 * 64 * VST)    // 26624
#define OFF_INV (OFF_RED + 128 * 16)       // 28672
#define OFF_MS  (OFF_INV + 128)            // 28800 floats; then 2*8192 mask bytes
#define ATTN_SMEM_BYTES (OFF_MS * 4 + 2 * 8192)   // 131584
__global__ __launch_bounds__(ATH) void attn_tc(float* __restrict__ attn_out)
{
    extern __shared__ float sm[];
    float* Ps   = sm;
    float* Ksb  = sm + OFF_KS;
    float* Vsb  = sm + OFF_VS;
    float* red  = sm + OFF_RED;
    float* invs = sm + OFF_INV;
    char*  Msb  = (char*)(sm + OFF_MS);

    const int t = threadIdx.x;
    const int lane = t & 31, w = t >> 5;
    const int g = lane >> 2, tig = lane & 3;
    const int wq = w >> 2, wn = w & 3;            // 4q x 4k warp grid
    const int qt = blockIdx.x, h = blockIdx.y, b = blockIdx.z;
    const int qg0 = qt * 128;
    const size_t qrowg = (size_t)(b * S_) + qg0;
    const int qlr = t >> 2, qseg = (t & 3) * 16;  // 128-row staging (16 floats/thread)
    const int kr = t >> 3, kq = t & 7;            // 64-row staging (8 floats/thread)

    const float* Kb = g_K + (size_t)(b * S_) * D_ + h * DK_;
    const float* Vb = g_V + (size_t)(b * S_) * D_ + h * DK_;
    const unsigned char* Mb = g_mask + (size_t)(b * S_ + qg0) * S_;
    const size_t attn_row0 = (size_t)(h * B_ + b) * S_ + qg0;

    // stage Q (pre-rounded) into Ps, lift fragments with exact *0.125 scale
    {
        const float* Qg = g_Q + (qrowg + qlr) * D_ + h * DK_ + qseg;
        float* dst = &Ps[qlr * AST + qseg];
#pragma unroll
        for (int jj = 0; jj < 4; jj++)
            *(float4*)(dst + 4 * jj) = *(const float4*)(Qg + 4 * jj);
    }
    __syncthreads();
    uint32_t qa[2][8][4];
#pragma unroll
    for (int i = 0; i < 2; i++) {
        const int r = 32 * wq + 16 * i + g;
#pragma unroll
        for (int ks = 0; ks < 8; ks++) {
            const int kd = ks * 8;
            qa[i][ks][0] = uf(SCALE_ * Ps[r * AST + kd + tig]);
            qa[i][ks][1] = uf(SCALE_ * Ps[(r + 8) * AST + kd + tig]);
            qa[i][ks][2] = uf(SCALE_ * Ps[r * AST + kd + tig + 4]);
            qa[i][ks][3] = uf(SCALE_ * Ps[(r + 8) * AST + kd + tig + 4]);
        }
    }

    // preload stage 0 (kc = 0)
    {
        float* dk = Ksb + kr * AST + kq * 8;
        float* dv = Vsb + kr * VST + kq * 8;
        const float* Kg = Kb + (size_t)kr * D_ + kq * 8;
        const float* Vg = Vb + (size_t)kr * D_ + kq * 8;
        cpa16(dk, Kg); cpa16(dk + 4, Kg + 4);
        cpa16(dv, Vg); cpa16(dv + 4, Vg + 4);
        char* dm = Msb + qlr * 64 + (t & 3) * 16;
        const unsigned char* mg = Mb + (size_t)qlr * S_ + (t & 3) * 16;
        cpa16(dm, mg);
        cpa_commit();
    }

    float rs[2][2] = {{0.f, 0.f}, {0.f, 0.f}};
    float4 o[2][2];
#pragma unroll
    for (int i = 0; i < 2; i++)
#pragma unroll
        for (int j = 0; j < 2; j++) o[i][j] = make_float4(0.f, 0.f, 0.f, 0.f);

    for (int ic = 0; ic < S_ / 64; ic++) {
        const int kc = ic * 64;
        cpa_wait0();
        __syncthreads();
        if (ic + 1 < S_ / 64) {
            const int st = (ic + 1) & 1;
            float* dk = Ksb + st * (64 * AST) + kr * AST + kq * 8;
            float* dv = Vsb + st * (64 * VST) + kr * VST + kq * 8;
            const float* Kg = Kb + (size_t)(kc + 64 + kr) * D_ + kq * 8;
            const float* Vg = Vb + (size_t)(kc + 64 + kr) * D_ + kq * 8;
            cpa16(dk, Kg); cpa16(dk + 4, Kg + 4);
            cpa16(dv, Vg); cpa16(dv + 4, Vg + 4);
            char* dm = Msb + st * 8192 + qlr * 64 + (t & 3) * 16;
            const unsigned char* mg = Mb + (size_t)qlr * S_ + kc + 64 + (t & 3) * 16;
            cpa16(dm, mg);
            cpa_commit();
        }
        const float* Ks = Ksb + (ic & 1) * (64 * AST);
        const float* Vs = Vsb + (ic & 1) * (64 * VST);
        const char*  Ms = Msb + (ic & 1) * 8192;

        // ---- QK: warp tile 32q x 16k
        float4 s[2][2];
#pragma unroll
        for (int i = 0; i < 2; i++)
#pragma unroll
            for (int j = 0; j < 2; j++) s[i][j] = make_float4(0.f, 0.f, 0.f, 0.f);
#pragma unroll
        for (int ks = 0; ks < 8; ks++) {
            const int kd = ks * 8;
            uint32_t bf[2][2];
#pragma unroll
            for (int j = 0; j < 2; j++) {
                const int n0 = 16 * wn + 8 * j + g;
                bf[j][0] = uf(Ks[n0 * AST + kd + tig]);
                bf[j][1] = uf(Ks[n0 * AST + kd + tig + 4]);
            }
#pragma unroll
            for (int i = 0; i < 2; i++)
#pragma unroll
                for (int j = 0; j < 2; j++) mma8(s[i][j], qa[i][ks], bf[j]);
        }

        // ---- exp + mask + rowsum; raw p -> gmem attn; tf32r(p) -> Ps
#pragma unroll
        for (int i = 0; i < 2; i++) {
            const int r = 32 * wq + 16 * i + g;
#pragma unroll
            for (int j = 0; j < 2; j++) {
                const int c0 = 16 * wn + 8 * j + 2 * tig;
                float p0 = Ms[r * 64 + c0]           ? 0.f : __expf(s[i][j].x);
                float p1 = Ms[r * 64 + c0 + 1]       ? 0.f : __expf(s[i][j].y);
                float p2 = Ms[(r + 8) * 64 + c0]     ? 0.f : __expf(s[i][j].z);
                float p3 = Ms[(r + 8) * 64 + c0 + 1] ? 0.f : __expf(s[i][j].w);
                rs[i][0] += p0 + p1; rs[i][1] += p2 + p3;
                *(float2*)(attn_out + (attn_row0 + r) * S_ + kc + c0)     = make_float2(p0, p1);
                *(float2*)(attn_out + (attn_row0 + r + 8) * S_ + kc + c0) = make_float2(p2, p3);
                Ps[r * AST + c0]           = tf32r(p0);
                Ps[r * AST + c0 + 1]       = tf32r(p1);
                Ps[(r + 8) * AST + c0]     = tf32r(p2);
                Ps[(r + 8) * AST + c0 + 1] = tf32r(p3);
            }
        }
        __syncthreads();

        // ---- PV (unnormalized accumulate): warp covers d-range 16*wn..+15
#pragma unroll
        for (int ks = 0; ks < 8; ks++) {
            const int kd = ks * 8;
            uint32_t pa[2][4], vb[2][2];
#pragma unroll
            for (int i = 0; i < 2; i++) {
                const int r = 32 * wq + 16 * i + g;
                pa[i][0] = uf(Ps[r * AST + kd + tig]);
                pa[i][1] = uf(Ps[(r + 8) * AST + kd + tig]);
                pa[i][2] = uf(Ps[r * AST + kd + tig + 4]);
                pa[i][3] = uf(Ps[(r + 8) * AST + kd + tig + 4]);
            }
#pragma unroll
            for (int j = 0; j < 2; j++) {
                const int d0 = 16 * wn + 8 * j + g;
                vb[j][0] = uf(Vs[(kd + tig) * VST + d0]);
                vb[j][1] = uf(Vs[(kd + tig + 4) * VST + d0]);
            }
#pragma unroll
            for (int i = 0; i < 2; i++)
#pragma unroll
                for (int j = 0; j < 2; j++) mma8(o[i][j], pa[i], vb[j]);
        }
    }

    // ---- rowsum reduction -> inv, g_inv (16 partials per row: 4 wn x 4 tig)
    __syncthreads();
#pragma unroll
    for (int i = 0; i < 2; i++) {
        const int r = 32 * wq + 16 * i + g;
        red[r * 16 + wn * 4 + tig]       = rs[i][0];
        red[(r + 8) * 16 + wn * 4 + tig] = rs[i][1];
    }
    __syncthreads();
    if (t < 128) {
        float ssum = 0.f;
#pragma unroll
        for (int j = 0; j < 16; j++) ssum += red[t * 16 + j];
        const float iv = 1.0f / ssum;
        invs[t] = iv;
        g_inv[attn_row0 + t] = iv;
    }
    __syncthreads();

    // ---- ctx epilogue: normalized + tf32-rounded, staged for coalesced store
#pragma unroll
    for (int i = 0; i < 2; i++) {
        const int r = 32 * wq + 16 * i + g;
        const float iv0 = invs[r], iv1 = invs[r + 8];
#pragma unroll
        for (int j = 0; j < 2; j++) {
            const int c0 = 16 * wn + 8 * j + 2 * tig;
            Ps[r * AST + c0]           = tf32r(o[i][j].x * iv0);
            Ps[r * AST + c0 + 1]       = tf32r(o[i][j].y * iv0);
            Ps[(r + 8) * AST + c0]     = tf32r(o[i][j].z * iv1);
            Ps[(r + 8) * AST + c0 + 1] = tf32r(o[i][j].w * iv1);
        }
    }
    __syncthreads();
    {
        float* cg = g_ctx + (qrowg + qlr) * D_ + h * DK_ + qseg;
        const float* src = &Ps[qlr * AST + qseg];
#pragma unroll
        for (int jj = 0; jj < 4; jj++)
            *(float4*)(cg + 4 * jj) = *(const float4*)(src + 4 * jj);
    }
}

// ---------------- attn normalization: attn *= 1/rowsum, MLP=4 + streaming ----
__global__ __launch_bounds__(256) void norm_attn_kernel(float* __restrict__ attn)
{
    const size_t n4 = NATTN / 4;
    const size_t gs = (size_t)gridDim.x * blockDim.x;
    float4* p = (float4*)attn;
    size_t i = (size_t)blockIdx.x * blockDim.x + threadIdx.x;
    for (; i + 3 * gs < n4; i += 4 * gs) {
        const size_t i0 = i, i1 = i + gs, i2 = i + 2 * gs, i3 = i + 3 * gs;
        float4 v0 = __ldcs(p + i0);
        float4 v1 = __ldcs(p + i1);
        float4 v2 = __ldcs(p + i2);
        float4 v3 = __ldcs(p + i3);
        const float a0 = g_inv[i0 >> 9], a1 = g_inv[i1 >> 9];
        const float a2 = g_inv[i2 >> 9], a3 = g_inv[i3 >> 9];
        v0.x *= a0; v0.y *= a0; v0.z *= a0; v0.w *= a0;
        v1.x *= a1; v1.y *= a1; v1.z *= a1; v1.w *= a1;
        v2.x *= a2; v2.y *= a2; v2.z *= a2; v2.w *= a2;
        v3.x *= a3; v3.y *= a3; v3.z *= a3; v3.w *= a3;
        __stcs(p + i0, v0);
        __stcs(p + i1, v1);
        __stcs(p + i2, v2);
        __stcs(p + i3, v3);
    }
    for (; i < n4; i += gs) {
        const float a = g_inv[i >> 9];
        float4 v = __ldcs(p + i);
        v.x *= a; v.y *= a; v.z *= a; v.w *= a;
        __stcs(p + i, v);
    }
}

// ---------------- layernorm --------------------------------------------------
__global__ __launch_bounds__(256) void ln_kernel(
    const float* __restrict__ X, const float* __restrict__ gamma,
    const float* __restrict__ beta, float* __restrict__ out)
{
    const int r = blockIdx.x;
    const int t = threadIdx.x;
    float4 v = *(const float4*)&X[(size_t)r * D_ + t * 4];
    float s  = v.x + v.y + v.z + v.w;
    float sq = v.x * v.x + v.y * v.y + v.z * v.z + v.w * v.w;
#pragma unroll
    for (int o = 16; o > 0; o >>= 1) {
        s  += __shfl_xor_sync(0xFFFFFFFFu, s, o);
        sq += __shfl_xor_sync(0xFFFFFFFFu, sq, o);
    }
    __shared__ float ws[8], wqv[8];
    const int w = t >> 5;
    if ((t & 31) == 0) { ws[w] = s; wqv[w] = sq; }
    __syncthreads();
    if (t < 32) {
        float a  = (t < 8) ? ws[t] : 0.0f;
        float b2 = (t < 8) ? wqv[t] : 0.0f;
#pragma unroll
        for (int o = 4; o > 0; o >>= 1) {
            a  += __shfl_xor_sync(0xFFFFFFFFu, a, o);
            b2 += __shfl_xor_sync(0xFFFFFFFFu, b2, o);
        }
        if (t == 0) { ws[0] = a; wqv[0] = b2; }
    }
    __syncthreads();
    const float mean = ws[0] * (1.0f / D_);
    const float var  = wqv[0] * (1.0f / D_) - mean * mean;
    const float rstd = rsqrtf(var + LN_EPS_);
    float4 gm = *(const float4*)&gamma[t * 4];
    float4 be = *(const float4*)&beta[t * 4];
    float4 o4;
    o4.x = gm.x * (v.x - mean) * rstd + be.x;
    o4.y = gm.y * (v.y - mean) * rstd + be.y;
    o4.z = gm.z * (v.z - mean) * rstd + be.z;
    o4.w = gm.w * (v.w - mean) * rstd + be.w;
    *(float4*)&out[(size_t)r * D_ + t * 4] = o4;
}

// ---------------- launch -----------------------------------------------------
extern "C" void kernel_launch(void* const* d_in, const int* in_sizes, int n_in,
                              void* d_out, int out_size)
{
    (void)in_sizes; (void)n_in; (void)out_size;
    const float* query = (const float*)d_in[0];
    const float* key   = (const float*)d_in[1];
    const float* value = (const float*)d_in[2];
    const void*  mask  = d_in[3];
    const float* Wq = (const float*)d_in[4];
    const float* bq = (const float*)d_in[5];
    const float* Wk = (const float*)d_in[6];
    const float* bk = (const float*)d_in[7];
    const float* Wv = (const float*)d_in[8];
    const float* bv = (const float*)d_in[9];
    const float* Wo = (const float*)d_in[10];
    const float* bo = (const float*)d_in[11];
    const float* gamma = (const float*)d_in[12];
    const float* beta  = (const float*)d_in[13];

    float* out  = (float*)d_out;
    float* attn = out + BSD;

    float* gCtx; cudaGetSymbolAddress((void**)&gCtx, g_ctx);
    float* gOut; cudaGetSymbolAddress((void**)&gOut, g_out);
    float* gWo;  cudaGetSymbolAddress((void**)&gWo,  g_Wo);

    cudaFuncSetAttribute(gemm_tc,  cudaFuncAttributeMaxDynamicSharedMemorySize, GEMM_SMEM_BYTES);
    cudaFuncSetAttribute(gemm_qkv, cudaFuncAttributeMaxDynamicSharedMemorySize, GEMM_SMEM_BYTES);
    cudaFuncSetAttribute(attn_tc,  cudaFuncAttributeMaxDynamicSharedMemorySize, ATTN_SMEM_BYTES);

    // launch order fixed so launch #6 (= ncu -s 5 -c 1 capture) is gemm_tc
    detect_mask_kernel<<<1, 256>>>((const unsigned int*)mask);           // 1
    convert_mask_kernel<<<4096, 256>>>(mask);                            // 2
    round_all<<<dim3(1024, 7), 256>>>(query, key, value, Wq, Wk, Wv, Wo); // 3

    dim3 gg(GN / 128, GM / 128);
    gemm_qkv<<<dim3(GN / 128, GM / 128, 3), 256, GEMM_SMEM_BYTES>>>(bq, bk, bv); // 4
    attn_tc<<<dim3(S_ / 128, H_, B_), ATH, ATTN_SMEM_BYTES>>>(attn);             // 5
    gemm_tc<<<gg, 256, GEMM_SMEM_BYTES>>>(gCtx, gWo, bo, query, gOut, 0);        // 6 <- profiled
    norm_attn_kernel<<<16384, 256>>>(attn);                                       // 7
    ln_kernel<<<B_ * S_, 256>>>(gOut, gamma, beta, out);                          // 8
}

// round 17
// speedup vs baseline: 1.0488x; 1.0034x over previous
#include <cuda_runtime.h>
#include <cstdint>

#define B_  4
#define S_  2048
#define D_  1024
#define H_  16
#define DK_ 64
#define SCALE_ 0.125f          // 1/sqrt(64), exact power of two
#define LN_EPS_ 1e-5f

#define GM 8192                // B_*S_
#define GN 1024
#define GK 1024

#define BSD ((size_t)B_ * S_ * D_)            // 8,388,608
#define NW  ((size_t)D_ * D_)                 // 1,048,576
#define NMASK ((size_t)B_ * S_ * S_)          // 16,777,216
#define NATTN ((size_t)B_ * H_ * S_ * S_)     // 268,435,456

// ---------------- device scratch --------------------------------------------
__device__ float g_Q[BSD];
__device__ float g_K[BSD];
__device__ float g_V[BSD];
__device__ float g_ctx[BSD];
__device__ float g_out[BSD];
__device__ float g_Xq[BSD];
__device__ float g_Xk[BSD];
__device__ float g_Xv[BSD];
__device__ float g_Wq[NW];
__device__ float g_Wk[NW];
__device__ float g_Wv[NW];
__device__ float g_Wo[NW];
__device__ float g_inv[(size_t)B_ * H_ * S_];
__device__ unsigned char g_mask[NMASK];

// ---------------- helpers ----------------------------------------------------
__device__ __forceinline__ float tf32r(float x) {
    uint32_t u; asm("cvt.rna.tf32.f32 %0, %1;" : "=r"(u) : "f"(x));
    return __uint_as_float(u);
}
__device__ __forceinline__ uint32_t uf(float x) { return __float_as_uint(x); }

__device__ __forceinline__ void mma8(float4& d, const uint32_t a[4], const uint32_t b[2]) {
    asm volatile(
        "mma.sync.aligned.m16n8k8.row.col.f32.tf32.tf32.f32 "
        "{%0,%1,%2,%3}, {%4,%5,%6,%7}, {%8,%9}, {%0,%1,%2,%3};"
        : "+f"(d.x), "+f"(d.y), "+f"(d.z), "+f"(d.w)
        : "r"(a[0]), "r"(a[1]), "r"(a[2]), "r"(a[3]), "r"(b[0]), "r"(b[1]));
}

__device__ __forceinline__ void cpa16(void* s, const void* g) {
    uint32_t sa = (uint32_t)__cvta_generic_to_shared(s);
    asm volatile("cp.async.cg.shared.global [%0], [%1], 16;" :: "r"(sa), "l"(g));
}
__device__ __forceinline__ void cpa_commit() { asm volatile("cp.async.commit_group;"); }
__device__ __forceinline__ void cpa_wait0()  { asm volatile("cp.async.wait_group 0;"); }

// ---------------- fused tf32 pre-round (RNA): 7 segments in one launch -------
__global__ __launch_bounds__(256) void round_all(
    const float* __restrict__ query, const float* __restrict__ key,
    const float* __restrict__ value, const float* __restrict__ Wq,
    const float* __restrict__ Wk, const float* __restrict__ Wv,
    const float* __restrict__ Wo)
{
    const int seg = blockIdx.y;
    const float* src; float* dst; size_t n4;
    switch (seg) {
        case 0: src = query; dst = g_Xq; n4 = BSD / 4; break;
        case 1: src = key;   dst = g_Xk; n4 = BSD / 4; break;
        case 2: src = value; dst = g_Xv; n4 = BSD / 4; break;
        case 3: src = Wq;    dst = g_Wq; n4 = NW / 4;  break;
        case 4: src = Wk;    dst = g_Wk; n4 = NW / 4;  break;
        case 5: src = Wv;    dst = g_Wv; n4 = NW / 4;  break;
        default: src = Wo;   dst = g_Wo; n4 = NW / 4;  break;
    }
    const size_t stride = (size_t)gridDim.x * blockDim.x;
    const float4* s4 = (const float4*)src;
    float4* d4 = (float4*)dst;
    for (size_t i = (size_t)blockIdx.x * blockDim.x + threadIdx.x; i < n4; i += stride) {
        float4 v = s4[i];
        d4[i] = make_float4(tf32r(v.x), tf32r(v.y), tf32r(v.z), tf32r(v.w));
    }
}

// ---------------- mask convert with inline dtype detection -------------------
// Every block classifies the dtype from the SAME first 8KB (L2-hot after the
// first block touches it); random 0/1 data makes disagreement ~2^-2048.
__global__ __launch_bounds__(256) void convert_mask_kernel(const void* __restrict__ mptr) {
    __shared__ unsigned int sh;
    if (threadIdx.x == 0) sh = 0u;
    __syncthreads();
    {
        const unsigned int* w = (const unsigned int*)mptr;
        unsigned int acc = 0u;
        for (int i = threadIdx.x; i < 2048; i += 256) acc |= w[i];
        atomicOr(&sh, acc);
    }
    __syncthreads();
    const unsigned int o = sh;
    int mode;
    if (o & 0x0000FF00u)              mode = 0; // uint8 bools (byte1 used)
    else if ((o & 0xFFFFFF00u) == 0u) mode = 1; // int32 0/1
    else                              mode = 2; // float32 0.0/1.0

    const size_t n = NMASK;
    const size_t stride = (size_t)gridDim.x * blockDim.x;
    for (size_t i = (size_t)blockIdx.x * blockDim.x + threadIdx.x; i < n; i += stride) {
        unsigned char v;
        if (mode == 0)      v = ((const unsigned char*)mptr)[i];
        else if (mode == 1) v = (unsigned char)(((const int*)mptr)[i] != 0);
        else                v = (unsigned char)(((const float*)mptr)[i] != 0.0f);
        g_mask[i] = v;
    }
}

// ---------------- tf32 TC GEMM body, cp.async + register frag pipeline -------
// C = A @ W^T + bias (+resid). A,W pre-rounded tf32. Block 128x128, kc=32.
// 8 warps = 4m x 2n, warp tile 32x64. Fragments double-buffered in registers
// so ks+1 loads overlap ks's MMA burst.
#define SA 36
#define GEMM_SMEM_BYTES (2 * 2 * 128 * SA * 4)   // 73728
__device__ __forceinline__ void gemm_load_frags(
    const float* __restrict__ as, const float* __restrict__ ws,
    int kc, int wq, int wn, int g, int tig,
    uint32_t a[2][4], uint32_t bfr[8][2])
{
#pragma unroll
    for (int i = 0; i < 2; i++) {
        const int r = 32 * wq + 16 * i + g;
        a[i][0] = uf(as[r * SA + kc + tig]);
        a[i][1] = uf(as[(r + 8) * SA + kc + tig]);
        a[i][2] = uf(as[r * SA + kc + tig + 4]);
        a[i][3] = uf(as[(r + 8) * SA + kc + tig + 4]);
    }
#pragma unroll
    for (int j = 0; j < 8; j++) {
        const int n0 = 64 * wn + 8 * j + g;
        bfr[j][0] = uf(ws[n0 * SA + kc + tig]);
        bfr[j][1] = uf(ws[n0 * SA + kc + tig + 4]);
    }
}

__device__ __forceinline__ void gemm_body(
    const float* __restrict__ A, const float* __restrict__ W,
    const float* __restrict__ bias, const float* __restrict__ resid,
    float* __restrict__ C, int round_out, int bx, int by, float* gsm)
{
    float* Asb = gsm;                      // 2 stages x 128*SA
    float* Wsb = gsm + 2 * 128 * SA;
    const int t = threadIdx.x;
    const int lane = t & 31, w = t >> 5;
    const int g = lane >> 2, tig = lane & 3;
    const int wq = w >> 1, wn = w & 1;
    const int bm = by * 128, bn = bx * 128;
    const int lrow = t >> 1, lseg = (t & 1) * 16;

    const float* Ag = A + (size_t)(bm + lrow) * GK + lseg;
    const float* Wg = W + (size_t)(bn + lrow) * GK + lseg;

    float4 acc[2][8];
#pragma unroll
    for (int i = 0; i < 2; i++)
#pragma unroll
        for (int j = 0; j < 8; j++) acc[i][j] = make_float4(0.f, 0.f, 0.f, 0.f);

    // preload stage 0
    {
        float* da = Asb + lrow * SA + lseg;
        float* dw = Wsb + lrow * SA + lseg;
#pragma unroll
        for (int p = 0; p < 4; p++) { cpa16(da + 4 * p, Ag + 4 * p); cpa16(dw + 4 * p, Wg + 4 * p); }
        cpa_commit();
    }

    uint32_t fa[2][2][4], fb[2][8][2];
    for (int it = 0; it < GK / 32; it++) {
        cpa_wait0();
        __syncthreads();
        if (it + 1 < GK / 32) {
            const int k0 = (it + 1) * 32;
            const int st = (it + 1) & 1;
            float* da = Asb + st * (128 * SA) + lrow * SA + lseg;
            float* dw = Wsb + st * (128 * SA) + lrow * SA + lseg;
#pragma unroll
            for (int p = 0; p < 4; p++) { cpa16(da + 4 * p, Ag + k0 + 4 * p); cpa16(dw + 4 * p, Wg + k0 + 4 * p); }
            cpa_commit();
        }
        const float* as = Asb + (it & 1) * (128 * SA);
        const float* ws = Wsb + (it & 1) * (128 * SA);

        gemm_load_frags(as, ws, 0, wq, wn, g, tig, fa[0], fb[0]);
#pragma unroll
        for (int ks = 0; ks < 4; ks++) {
            if (ks < 3)
                gemm_load_frags(as, ws, (ks + 1) * 8, wq, wn, g, tig,
                                fa[(ks + 1) & 1], fb[(ks + 1) & 1]);
            const int cur = ks & 1;
#pragma unroll
            for (int i = 0; i < 2; i++)
#pragma unroll
                for (int j = 0; j < 8; j++) mma8(acc[i][j], fa[cur][i], fb[cur][j]);
        }
    }
#pragma unroll
    for (int i = 0; i < 2; i++) {
        const int r0 = bm + 32 * wq + 16 * i + g;
#pragma unroll
        for (int j = 0; j < 8; j++) {
            const int cg = bn + 64 * wn + 8 * j + 2 * tig;
            float2 bb = *(const float2*)&bias[cg];
            float2 o0 = make_float2(acc[i][j].x + bb.x, acc[i][j].y + bb.y);
            float2 o1 = make_float2(acc[i][j].z + bb.x, acc[i][j].w + bb.y);
            if (resid) {
                float2 ra = *(const float2*)&resid[(size_t)r0 * GN + cg];
                float2 rb = *(const float2*)&resid[(size_t)(r0 + 8) * GN + cg];
                o0.x += ra.x; o0.y += ra.y; o1.x += rb.x; o1.y += rb.y;
            }
            if (round_out) {
                o0.x = tf32r(o0.x); o0.y = tf32r(o0.y);
                o1.x = tf32r(o1.x); o1.y = tf32r(o1.y);
            }
            *(float2*)&C[(size_t)r0 * GN + cg] = o0;
            *(float2*)&C[(size_t)(r0 + 8) * GN + cg] = o1;
        }
    }
}

__global__ __launch_bounds__(256, 2) void gemm_tc(
    const float* __restrict__ A, const float* __restrict__ W,
    const float* __restrict__ bias, const float* __restrict__ resid,
    float* __restrict__ C, int round_out)
{
    extern __shared__ float gsm[];
    gemm_body(A, W, bias, resid, C, round_out, blockIdx.x, blockIdx.y, gsm);
}

// fused Q/K/V projections: grid.z selects the triple
__global__ __launch_bounds__(256, 2) void gemm_qkv(
    const float* __restrict__ bq, const float* __restrict__ bk,
    const float* __restrict__ bv)
{
    extern __shared__ float gsm[];
    const int z = blockIdx.z;
    const float* A    = (z == 0) ? g_Xq : (z == 1) ? g_Xk : g_Xv;
    const float* W    = (z == 0) ? g_Wq : (z == 1) ? g_Wk : g_Wv;
    const float* bias = (z == 0) ? bq   : (z == 1) ? bk   : bv;
    float* C          = (z == 0) ? g_Q  : (z == 1) ? g_K  : g_V;
    gemm_body(A, W, bias, nullptr, C, 1, blockIdx.x, blockIdx.y, gsm);
}

// ---------------- single-pass TC attention, 512 threads (16 warps) -----------
// qtile=128, ktile=64. Warp grid 4q x 4k; warp tile 32x16. Q frags in regs.
// Writes UNNORMALIZED exp to attn (sector-aligned float2 stores), rowsum inv
// to g_inv, tf32-rounded normalized ctx to g_ctx.
#define ATH 512
#define AST 68   // Q/K/P stride (272B, 16B-aligned)
#define VST 72   // V stride (288B)
#define OFF_KS  8704                       // Ps = 128*AST = 8704 floats
#define OFF_VS  (OFF_KS + 2 * 64 * AST)    // 17408
#define OFF_RED (OFF_VS + 2 * 64 * VST)    // 26624
#define OFF_INV (OFF_RED + 128 * 16)       // 28672
#define OFF_MS  (OFF_INV + 128)            // 28800 floats; then 2*8192 mask bytes
#define ATTN_SMEM_BYTES (OFF_MS * 4 + 2 * 8192)   // 131584
__global__ __launch_bounds__(ATH) void attn_tc(float* __restrict__ attn_out)
{
    extern __shared__ float sm[];
    float* Ps   = sm;
    float* Ksb  = sm + OFF_KS;
    float* Vsb  = sm + OFF_VS;
    float* red  = sm + OFF_RED;
    float* invs = sm + OFF_INV;
    char*  Msb  = (char*)(sm + OFF_MS);

    const int t = threadIdx.x;
    const int lane = t & 31, w = t >> 5;
    const int g = lane >> 2, tig = lane & 3;
    const int wq = w >> 2, wn = w & 3;            // 4q x 4k warp grid
    const int qt = blockIdx.x, h = blockIdx.y, b = blockIdx.z;
    const int qg0 = qt * 128;
    const size_t qrowg = (size_t)(b * S_) + qg0;
    const int qlr = t >> 2, qseg = (t & 3) * 16;  // 128-row staging (16 floats/thread)
    const int kr = t >> 3, kq = t & 7;            // 64-row staging (8 floats/thread)

    const float* Kb = g_K + (size_t)(b * S_) * D_ + h * DK_;
    const float* Vb = g_V + (size_t)(b * S_) * D_ + h * DK_;
    const unsigned char* Mb = g_mask + (size_t)(b * S_ + qg0) * S_;
    const size_t attn_row0 = (size_t)(h * B_ + b) * S_ + qg0;

    // stage Q (pre-rounded) into Ps, lift fragments with exact *0.125 scale
    {
        const float* Qg = g_Q + (qrowg + qlr) * D_ + h * DK_ + qseg;
        float* dst = &Ps[qlr * AST + qseg];
#pragma unroll
        for (int jj = 0; jj < 4; jj++)
            *(float4*)(dst + 4 * jj) = *(const float4*)(Qg + 4 * jj);
    }
    __syncthreads();
    uint32_t qa[2][8][4];
#pragma unroll
    for (int i = 0; i < 2; i++) {
        const int r = 32 * wq + 16 * i + g;
#pragma unroll
        for (int ks = 0; ks < 8; ks++) {
            const int kd = ks * 8;
            qa[i][ks][0] = uf(SCALE_ * Ps[r * AST + kd + tig]);
            qa[i][ks][1] = uf(SCALE_ * Ps[(r + 8) * AST + kd + tig]);
            qa[i][ks][2] = uf(SCALE_ * Ps[r * AST + kd + tig + 4]);
            qa[i][ks][3] = uf(SCALE_ * Ps[(r + 8) * AST + kd + tig + 4]);
        }
    }

    // preload stage 0 (kc = 0)
    {
        float* dk = Ksb + kr * AST + kq * 8;
        float* dv = Vsb + kr * VST + kq * 8;
        const float* Kg = Kb + (size_t)kr * D_ + kq * 8;
        const float* Vg = Vb + (size_t)kr * D_ + kq * 8;
        cpa16(dk, Kg); cpa16(dk + 4, Kg + 4);
        cpa16(dv, Vg); cpa16(dv + 4, Vg + 4);
        char* dm = Msb + qlr * 64 + (t & 3) * 16;
        const unsigned char* mg = Mb + (size_t)qlr * S_ + (t & 3) * 16;
        cpa16(dm, mg);
        cpa_commit();
    }

    float rs[2][2] = {{0.f, 0.f}, {0.f, 0.f}};
    float4 o[2][2];
#pragma unroll
    for (int i = 0; i < 2; i++)
#pragma unroll
        for (int j = 0; j < 2; j++) o[i][j] = make_float4(0.f, 0.f, 0.f, 0.f);

    for (int ic = 0; ic < S_ / 64; ic++) {
        const int kc = ic * 64;
        cpa_wait0();
        __syncthreads();
        if (ic + 1 < S_ / 64) {
            const int st = (ic + 1) & 1;
            float* dk = Ksb + st * (64 * AST) + kr * AST + kq * 8;
            float* dv = Vsb + st * (64 * VST) + kr * VST + kq * 8;
            const float* Kg = Kb + (size_t)(kc + 64 + kr) * D_ + kq * 8;
            const float* Vg = Vb + (size_t)(kc + 64 + kr) * D_ + kq * 8;
            cpa16(dk, Kg); cpa16(dk + 4, Kg + 4);
            cpa16(dv, Vg); cpa16(dv + 4, Vg + 4);
            char* dm = Msb + st * 8192 + qlr * 64 + (t & 3) * 16;
            const unsigned char* mg = Mb + (size_t)qlr * S_ + kc + 64 + (t & 3) * 16;
            cpa16(dm, mg);
            cpa_commit();
        }
        const float* Ks = Ksb + (ic & 1) * (64 * AST);
        const float* Vs = Vsb + (ic & 1) * (64 * VST);
        const char*  Ms = Msb + (ic & 1) * 8192;

        // ---- QK: warp tile 32q x 16k
        float4 s[2][2];
#pragma unroll
        for (int i = 0; i < 2; i++)
#pragma unroll
            for (int j = 0; j < 2; j++) s[i][j] = make_float4(0.f, 0.f, 0.f, 0.f);
#pragma unroll
        for (int ks = 0; ks < 8; ks++) {
            const int kd = ks * 8;
            uint32_t bf[2][2];
#pragma unroll
            for (int j = 0; j < 2; j++) {
                const int n0 = 16 * wn + 8 * j + g;
                bf[j][0] = uf(Ks[n0 * AST + kd + tig]);
                bf[j][1] = uf(Ks[n0 * AST + kd + tig + 4]);
            }
#pragma unroll
            for (int i = 0; i < 2; i++)
#pragma unroll
                for (int j = 0; j < 2; j++) mma8(s[i][j], qa[i][ks], bf[j]);
        }

        // ---- exp + mask + rowsum; raw p -> gmem attn; tf32r(p) -> Ps
#pragma unroll
        for (int i = 0; i < 2; i++) {
            const int r = 32 * wq + 16 * i + g;
#pragma unroll
            for (int j = 0; j < 2; j++) {
                const int c0 = 16 * wn + 8 * j + 2 * tig;
                float p0 = Ms[r * 64 + c0]           ? 0.f : __expf(s[i][j].x);
                float p1 = Ms[r * 64 + c0 + 1]       ? 0.f : __expf(s[i][j].y);
                float p2 = Ms[(r + 8) * 64 + c0]     ? 0.f : __expf(s[i][j].z);
                float p3 = Ms[(r + 8) * 64 + c0 + 1] ? 0.f : __expf(s[i][j].w);
                rs[i][0] += p0 + p1; rs[i][1] += p2 + p3;
                *(float2*)(attn_out + (attn_row0 + r) * S_ + kc + c0)     = make_float2(p0, p1);
                *(float2*)(attn_out + (attn_row0 + r + 8) * S_ + kc + c0) = make_float2(p2, p3);
                Ps[r * AST + c0]           = tf32r(p0);
                Ps[r * AST + c0 + 1]       = tf32r(p1);
                Ps[(r + 8) * AST + c0]     = tf32r(p2);
                Ps[(r + 8) * AST + c0 + 1] = tf32r(p3);
            }
        }
        __syncthreads();

        // ---- PV (unnormalized accumulate): warp covers d-range 16*wn..+15
#pragma unroll
        for (int ks = 0; ks < 8; ks++) {
            const int kd = ks * 8;
            uint32_t pa[2][4], vb[2][2];
#pragma unroll
            for (int i = 0; i < 2; i++) {
                const int r = 32 * wq + 16 * i + g;
                pa[i][0] = uf(Ps[r * AST + kd + tig]);
                pa[i][1] = uf(Ps[(r + 8) * AST + kd + tig]);
                pa[i][2] = uf(Ps[r * AST + kd + tig + 4]);
                pa[i][3] = uf(Ps[(r + 8) * AST + kd + tig + 4]);
            }
#pragma unroll
            for (int j = 0; j < 2; j++) {
                const int d0 = 16 * wn + 8 * j + g;
                vb[j][0] = uf(Vs[(kd + tig) * VST + d0]);
                vb[j][1] = uf(Vs[(kd + tig + 4) * VST + d0]);
            }
#pragma unroll
            for (int i = 0; i < 2; i++)
#pragma unroll
                for (int j = 0; j < 2; j++) mma8(o[i][j], pa[i], vb[j]);
        }
    }

    // ---- rowsum reduction -> inv, g_inv (16 partials per row: 4 wn x 4 tig)
    __syncthreads();
#pragma unroll
    for (int i = 0; i < 2; i++) {
        const int r = 32 * wq + 16 * i + g;
        red[r * 16 + wn * 4 + tig]       = rs[i][0];
        red[(r + 8) * 16 + wn * 4 + tig] = rs[i][1];
    }
    __syncthreads();
    if (t < 128) {
        float ssum = 0.f;
#pragma unroll
        for (int j = 0; j < 16; j++) ssum += red[t * 16 + j];
        const float iv = 1.0f / ssum;
        invs[t] = iv;
        g_inv[attn_row0 + t] = iv;
    }
    __syncthreads();

    // ---- ctx epilogue: normalized + tf32-rounded, staged for coalesced store
#pragma unroll
    for (int i = 0; i < 2; i++) {
        const int r = 32 * wq + 16 * i + g;
        const float iv0 = invs[r], iv1 = invs[r + 8];
#pragma unroll
        for (int j = 0; j < 2; j++) {
            const int c0 = 16 * wn + 8 * j + 2 * tig;
            Ps[r * AST + c0]           = tf32r(o[i][j].x * iv0);
            Ps[r * AST + c0 + 1]       = tf32r(o[i][j].y * iv0);
            Ps[(r + 8) * AST + c0]     = tf32r(o[i][j].z * iv1);
            Ps[(r + 8) * AST + c0 + 1] = tf32r(o[i][j].w * iv1);
        }
    }
    __syncthreads();
    {
        float* cg = g_ctx + (qrowg + qlr) * D_ + h * DK_ + qseg;
        const float* src = &Ps[qlr * AST + qseg];
#pragma unroll
        for (int jj = 0; jj < 4; jj++)
            *(float4*)(cg + 4 * jj) = *(const float4*)(src + 4 * jj);
    }
}

// ---------------- attn normalization: attn *= 1/rowsum, MLP=4 + streaming ----
__global__ __launch_bounds__(256) void norm_attn_kernel(float* __restrict__ attn)
{
    const size_t n4 = NATTN / 4;
    const size_t gs = (size_t)gridDim.x * blockDim.x;
    float4* p = (float4*)attn;
    size_t i = (size_t)blockIdx.x * blockDim.x + threadIdx.x;
    for (; i + 3 * gs < n4; i += 4 * gs) {
        const size_t i0 = i, i1 = i + gs, i2 = i + 2 * gs, i3 = i + 3 * gs;
        float4 v0 = __ldcs(p + i0);
        float4 v1 = __ldcs(p + i1);
        float4 v2 = __ldcs(p + i2);
        float4 v3 = __ldcs(p + i3);
        const float a0 = g_inv[i0 >> 9], a1 = g_inv[i1 >> 9];
        const float a2 = g_inv[i2 >> 9], a3 = g_inv[i3 >> 9];
        v0.x *= a0; v0.y *= a0; v0.z *= a0; v0.w *= a0;
        v1.x *= a1; v1.y *= a1; v1.z *= a1; v1.w *= a1;
        v2.x *= a2; v2.y *= a2; v2.z *= a2; v2.w *= a2;
        v3.x *= a3; v3.y *= a3; v3.z *= a3; v3.w *= a3;
        __stcs(p + i0, v0);
        __stcs(p + i1, v1);
        __stcs(p + i2, v2);
        __stcs(p + i3, v3);
    }
    for (; i < n4; i += gs) {
        const float a = g_inv[i >> 9];
        float4 v = __ldcs(p + i);
        v.x *= a; v.y *= a; v.z *= a; v.w *= a;
        __stcs(p + i, v);
    }
}

// ---------------- layernorm --------------------------------------------------
__global__ __launch_bounds__(256) void ln_kernel(
    const float* __restrict__ X, const float* __restrict__ gamma,
    const float* __restrict__ beta, float* __restrict__ out)
{
    const int r = blockIdx.x;
    const int t = threadIdx.x;
    float4 v = *(const float4*)&X[(size_t)r * D_ + t * 4];
    float s  = v.x + v.y + v.z + v.w;
    float sq = v.x * v.x + v.y * v.y + v.z * v.z + v.w * v.w;
#pragma unroll
    for (int o = 16; o > 0; o >>= 1) {
        s  += __shfl_xor_sync(0xFFFFFFFFu, s, o);
        sq += __shfl_xor_sync(0xFFFFFFFFu, sq, o);
    }
    __shared__ float ws[8], wqv[8];
    const int w = t >> 5;
    if ((t & 31) == 0) { ws[w] = s; wqv[w] = sq; }
    __syncthreads();
    if (t < 32) {
        float a  = (t < 8) ? ws[t] : 0.0f;
        float b2 = (t < 8) ? wqv[t] : 0.0f;
#pragma unroll
        for (int o = 4; o > 0; o >>= 1) {
            a  += __shfl_xor_sync(0xFFFFFFFFu, a, o);
            b2 += __shfl_xor_sync(0xFFFFFFFFu, b2, o);
        }
        if (t == 0) { ws[0] = a; wqv[0] = b2; }
    }
    __syncthreads();
    const float mean = ws[0] * (1.0f / D_);
    const float var  = wqv[0] * (1.0f / D_) - mean * mean;
    const float rstd = rsqrtf(var + LN_EPS_);
    float4 gm = *(const float4*)&gamma[t * 4];
    float4 be = *(const float4*)&beta[t * 4];
    float4 o4;
    o4.x = gm.x * (v.x - mean) * rstd + be.x;
    o4.y = gm.y * (v.y - mean) * rstd + be.y;
    o4.z = gm.z * (v.z - mean) * rstd + be.z;
    o4.w = gm.w * (v.w - mean) * rstd + be.w;
    *(float4*)&out[(size_t)r * D_ + t * 4] = o4;
}

// ---------------- launch -----------------------------------------------------
extern "C" void kernel_launch(void* const* d_in, const int* in_sizes, int n_in,
                              void* d_out, int out_size)
{
    (void)in_sizes; (void)n_in; (void)out_size;
    const float* query = (const float*)d_in[0];
    const float* key   = (const float*)d_in[1];
    const float* value = (const float*)d_in[2];
    const void*  mask  = d_in[3];
    const float* Wq = (const float*)d_in[4];
    const float* bq = (const float*)d_in[5];
    const float* Wk = (const float*)d_in[6];
    const float* bk = (const float*)d_in[7];
    const float* Wv = (const float*)d_in[8];
    const float* bv = (const float*)d_in[9];
    const float* Wo = (const float*)d_in[10];
    const float* bo = (const float*)d_in[11];
    const float* gamma = (const float*)d_in[12];
    const float* beta  = (const float*)d_in[13];

    float* out  = (float*)d_out;
    float* attn = out + BSD;

    float* gCtx; cudaGetSymbolAddress((void**)&gCtx, g_ctx);
    float* gOut; cudaGetSymbolAddress((void**)&gOut, g_out);
    float* gWo;  cudaGetSymbolAddress((void**)&gWo,  g_Wo);

    cudaFuncSetAttribute(gemm_tc,  cudaFuncAttributeMaxDynamicSharedMemorySize, GEMM_SMEM_BYTES);
    cudaFuncSetAttribute(gemm_qkv, cudaFuncAttributeMaxDynamicSharedMemorySize, GEMM_SMEM_BYTES);
    cudaFuncSetAttribute(attn_tc,  cudaFuncAttributeMaxDynamicSharedMemorySize, ATTN_SMEM_BYTES);

    // launch order: slot #4 (ncu-profiled) = attn_tc
    convert_mask_kernel<<<4096, 256>>>(mask);                             // 1
    round_all<<<dim3(1024, 7), 256>>>(query, key, value, Wq, Wk, Wv, Wo); // 2
    gemm_qkv<<<dim3(GN / 128, GM / 128, 3), 256, GEMM_SMEM_BYTES>>>(bq, bk, bv); // 3
    attn_tc<<<dim3(S_ / 128, H_, B_), ATH, ATTN_SMEM_BYTES>>>(attn);             // 4 <- profiled
    gemm_tc<<<dim3(GN / 128, GM / 128), 256, GEMM_SMEM_BYTES>>>(gCtx, gWo, bo, query, gOut, 0); // 5
    norm_attn_kernel<<<16384, 256>>>(attn);                                       // 6
    ln_kernel<<<B_ * S_, 256>>>(gOut, gamma, beta, out);                          // 7
}